// round 4
// baseline (speedup 1.0000x reference)
#include <cuda_runtime.h>
#include <cstdint>
#include <math.h>

// Problem constants
#define T_TOK 4096
#define H_DIM 2048
#define E_NUM 32
#define I_DIM 1024
#define TOPK  8
#define P_NUM (T_TOK * TOPK)

// ---------------- scratch ----------------
__device__ int   g_topk_ids[P_NUM];
__device__ float g_topk_w[P_NUM];
__device__ int   g_cnt[E_NUM];
__device__ int   g_pos[E_NUM];
__device__ int   g_off[E_NUM + 1];
__device__ int   g_slot_token[P_NUM];
__device__ float g_slot_w[P_NUM];
__device__ int   g_pair2slot[P_NUM];
__device__ float g_hbuf[(size_t)P_NUM * I_DIM];
__device__ float g_dbuf[(size_t)P_NUM * H_DIM];

// ---------------- helpers ----------------
__device__ __forceinline__ uint32_t f2tf(float f) {
    uint32_t u;
    asm("cvt.rna.tf32.f32 %0, %1;" : "=r"(u) : "f"(f));
    return u;
}

__device__ __forceinline__ void mma8(float c[4], const uint32_t a[4], const uint32_t b[2]) {
    asm volatile(
        "mma.sync.aligned.m16n8k8.row.col.f32.tf32.tf32.f32 "
        "{%0,%1,%2,%3}, {%4,%5,%6,%7}, {%8,%9}, {%0,%1,%2,%3};\n"
        : "+f"(c[0]), "+f"(c[1]), "+f"(c[2]), "+f"(c[3])
        : "r"(a[0]), "r"(a[1]), "r"(a[2]), "r"(a[3]), "r"(b[0]), "r"(b[1]));
}

__device__ __forceinline__ void cpa16(uint32_t saddr, const void* g) {
    asm volatile("cp.async.cg.shared.global [%0], [%1], 16;" :: "r"(saddr), "l"(g));
}
#define CP_COMMIT() asm volatile("cp.async.commit_group;")
#define CP_WAIT(N)  asm volatile("cp.async.wait_group %0;" :: "n"(N))

__device__ __forceinline__ float silu(float x) {
    return x * (1.0f / (1.0f + __expf(-x)));
}

// ---------------- kernel 0 ----------------
__global__ void k_zero() {
    if (threadIdx.x < E_NUM) g_cnt[threadIdx.x] = 0;
}

// ---------------- kernel 1: router ----------------
__global__ void k_router(const float* __restrict__ x, const float* __restrict__ gw,
                         float* __restrict__ out, int write_ids) {
    int warp = (blockIdx.x * blockDim.x + threadIdx.x) >> 5;
    int lane = threadIdx.x & 31;
    if (warp >= T_TOK) return;

    const float* xr = x + (size_t)warp * H_DIM;
    float acc = 0.0f;
#pragma unroll 8
    for (int h = 0; h < H_DIM; h++) acc += xr[h] * gw[h * E_NUM + lane];

    float m = acc;
#pragma unroll
    for (int o = 16; o; o >>= 1) m = fmaxf(m, __shfl_xor_sync(0xffffffffu, m, o));
    float p = expf(acc - m);
    float s = p;
#pragma unroll
    for (int o = 16; o; o >>= 1) s += __shfl_xor_sync(0xffffffffu, s, o);
    float score = p / s;

    float val = score;
    int   ids[TOPK];
    float ws[TOPK];
    float wsum = 0.0f;
#pragma unroll
    for (int j = 0; j < TOPK; j++) {
        float bv = val;
        int   bi = lane;
#pragma unroll
        for (int o = 16; o; o >>= 1) {
            float ov = __shfl_xor_sync(0xffffffffu, bv, o);
            int   oi = __shfl_xor_sync(0xffffffffu, bi, o);
            if (ov > bv || (ov == bv && oi < bi)) { bv = ov; bi = oi; }
        }
        ids[j] = bi; ws[j] = bv; wsum += bv;
        if (lane == bi) val = -1.0f;
    }

    if (lane == 0) {
        float inv = 1.0f / wsum;
#pragma unroll
        for (int j = 0; j < TOPK; j++) {
            g_topk_ids[warp * TOPK + j] = ids[j];
            g_topk_w[warp * TOPK + j]   = ws[j] * inv;
            atomicAdd(&g_cnt[ids[j]], 1);
            if (write_ids)
                out[(size_t)T_TOK * H_DIM + warp * TOPK + j] = (float)ids[j];
        }
    }
}

// ---------------- kernel 2/3 ----------------
__global__ void k_scan() {
    if (threadIdx.x == 0) {
        int acc = 0;
        for (int e = 0; e < E_NUM; e++) { g_off[e] = acc; g_pos[e] = acc; acc += g_cnt[e]; }
        g_off[E_NUM] = acc;
    }
}

__global__ void k_scatter() {
    int pp = blockIdx.x * blockDim.x + threadIdx.x;
    if (pp >= P_NUM) return;
    int e = g_topk_ids[pp];
    int slot = atomicAdd(&g_pos[e], 1);
    g_slot_token[slot] = pp >> 3;
    g_slot_w[slot]     = g_topk_w[pp];
    g_pair2slot[pp]    = slot;
}

// ================= kernel 4: fused gate+up GEMM + SwiGLU =================
// Block 128M x 64N, BK=32, 2-stage cp.async pipeline, 8 warps (4M x 2N), warp 32x32.
#define A_STRIDE 36            // floats per A smem row (32 + pad)
#define A_TILE   (128 * A_STRIDE)   // 4608 floats / stage
#define BG_STRIDE 68           // floats per B smem row (64 + pad)
#define BG_TILE  (32 * BG_STRIDE)   // 2176 floats / stage

__global__ __launch_bounds__(256) void k_gemmA(const float* __restrict__ x,
                                               const float* __restrict__ wgate,
                                               const float* __restrict__ wup) {
    int e   = blockIdx.z;
    int cnt = g_cnt[e];
    int m0  = blockIdx.y * 128;
    if (m0 >= cnt) return;
    int n0   = blockIdx.x * 64;
    int base = g_off[e];
    int tid  = threadIdx.x;

    extern __shared__ float smem[];
    // layout: As[2] | Bg[2] | Bu[2]
    float* AsB = smem;
    float* BgB = smem + 2 * A_TILE;
    float* BuB = smem + 2 * A_TILE + 2 * BG_TILE;
    uint32_t sbase = (uint32_t)__cvta_generic_to_shared(smem);

    __shared__ int s_tok[128];
    if (tid < 128) {
        int m = m0 + tid;
        s_tok[tid] = g_slot_token[base + ((m < cnt) ? m : 0)];
    }
    __syncthreads();

    const float* wgb = wgate + (size_t)e * H_DIM * I_DIM + n0;
    const float* wub = wup   + (size_t)e * H_DIM * I_DIM + n0;

    // cp.async staging coords
    int ac = tid & 7,  ar = tid >> 3;     // A: 8 chunks/row, 32 rows/pass, 4 passes
    int bc = tid & 15, br = tid >> 4;     // B: 16 chunks/row, 16 rows/pass, 2 passes

    const int NT = H_DIM / 32;  // 64

    auto load_stage = [&](int t, int s) {
        int k0 = t * 32;
        uint32_t aoff = sbase + (uint32_t)(s * A_TILE) * 4u;
        uint32_t goff = sbase + (uint32_t)(2 * A_TILE + s * BG_TILE) * 4u;
        uint32_t uoff = sbase + (uint32_t)(2 * A_TILE + 2 * BG_TILE + s * BG_TILE) * 4u;
#pragma unroll
        for (int i = 0; i < 4; i++) {
            int r = ar + i * 32;
            const float* gp = x + (size_t)s_tok[r] * H_DIM + k0 + ac * 4;
            cpa16(aoff + (uint32_t)(r * A_STRIDE + ac * 4) * 4u, gp);
        }
#pragma unroll
        for (int i = 0; i < 2; i++) {
            int kr = br + i * 16;
            uint32_t so = (uint32_t)(kr * BG_STRIDE + bc * 4) * 4u;
            cpa16(goff + so, wgb + (size_t)(k0 + kr) * I_DIM + bc * 4);
            cpa16(uoff + so, wub + (size_t)(k0 + kr) * I_DIM + bc * 4);
        }
        CP_COMMIT();
    };

    int wid = tid >> 5, lane = tid & 31;
    int wm = (wid & 3) * 32, wn = (wid >> 2) * 32;
    int gid = lane >> 2, tig = lane & 3;

    float cg[2][4][4], cu[2][4][4];
#pragma unroll
    for (int i = 0; i < 2; i++)
#pragma unroll
        for (int j = 0; j < 4; j++)
#pragma unroll
            for (int q = 0; q < 4; q++) { cg[i][j][q] = 0.0f; cu[i][j][q] = 0.0f; }

    load_stage(0, 0);

    for (int t = 0; t < NT; t++) {
        if (t + 1 < NT) { load_stage(t + 1, (t + 1) & 1); CP_WAIT(1); }
        else            { CP_WAIT(0); }
        __syncthreads();

        const float* As = AsB + (t & 1) * A_TILE;
        const float* Bg = BgB + (t & 1) * BG_TILE;
        const float* Bu = BuB + (t & 1) * BG_TILE;

#pragma unroll
        for (int kf = 0; kf < 32; kf += 8) {
            uint32_t a[2][4];
#pragma unroll
            for (int mf = 0; mf < 2; mf++) {
                int rb = wm + mf * 16;
                a[mf][0] = f2tf(As[(rb + gid) * A_STRIDE + kf + tig]);
                a[mf][1] = f2tf(As[(rb + gid + 8) * A_STRIDE + kf + tig]);
                a[mf][2] = f2tf(As[(rb + gid) * A_STRIDE + kf + tig + 4]);
                a[mf][3] = f2tf(As[(rb + gid + 8) * A_STRIDE + kf + tig + 4]);
            }
            uint32_t bg[4][2], bu[4][2];
#pragma unroll
            for (int nf = 0; nf < 4; nf++) {
                int cb = wn + nf * 8 + gid;
                bg[nf][0] = f2tf(Bg[(kf + tig) * BG_STRIDE + cb]);
                bg[nf][1] = f2tf(Bg[(kf + tig + 4) * BG_STRIDE + cb]);
                bu[nf][0] = f2tf(Bu[(kf + tig) * BG_STRIDE + cb]);
                bu[nf][1] = f2tf(Bu[(kf + tig + 4) * BG_STRIDE + cb]);
            }
#pragma unroll
            for (int mf = 0; mf < 2; mf++)
#pragma unroll
                for (int nf = 0; nf < 4; nf++) {
                    mma8(cg[mf][nf], a[mf], bg[nf]);
                    mma8(cu[mf][nf], a[mf], bu[nf]);
                }
        }
        __syncthreads();
    }

    // epilogue
#pragma unroll
    for (int mf = 0; mf < 2; mf++)
#pragma unroll
        for (int nf = 0; nf < 4; nf++) {
            int col = n0 + wn + nf * 8 + 2 * tig;
            int r1 = wm + mf * 16 + gid;
            int r2 = r1 + 8;
            int m1 = m0 + r1, m2 = m0 + r2;
            if (m1 < cnt) {
                float2 v = make_float2(silu(cg[mf][nf][0]) * cu[mf][nf][0],
                                       silu(cg[mf][nf][1]) * cu[mf][nf][1]);
                *(float2*)&g_hbuf[(size_t)(base + m1) * I_DIM + col] = v;
            }
            if (m2 < cnt) {
                float2 v = make_float2(silu(cg[mf][nf][2]) * cu[mf][nf][2],
                                       silu(cg[mf][nf][3]) * cu[mf][nf][3]);
                *(float2*)&g_hbuf[(size_t)(base + m2) * I_DIM + col] = v;
            }
        }
}

// ================= kernel 5: down GEMM (weighted) =================
// Block 128M x 128N, BK=32, 2-stage cp.async, 8 warps (4M x 2N), warp 32x64.
#define BD_STRIDE 132
#define BD_TILE   (32 * BD_STRIDE)   // 4224 floats / stage

__global__ __launch_bounds__(256) void k_gemmB(const float* __restrict__ wdown) {
    int e   = blockIdx.z;
    int cnt = g_cnt[e];
    int m0  = blockIdx.y * 128;
    if (m0 >= cnt) return;
    int n0   = blockIdx.x * 128;
    int base = g_off[e];
    int tid  = threadIdx.x;

    extern __shared__ float smem[];
    float* AsB = smem;
    float* BsB = smem + 2 * A_TILE;
    uint32_t sbase = (uint32_t)__cvta_generic_to_shared(smem);

    const float* wb = wdown + (size_t)e * I_DIM * H_DIM + n0;

    int ac = tid & 7,  ar = tid >> 3;     // A: 8 chunks/row, 32 rows/pass, 4 passes
    int bc = tid & 31, br = tid >> 5;     // B: 32 chunks/row, 8 rows/pass, 4 passes

    const int NT = I_DIM / 32;  // 32

    auto load_stage = [&](int t, int s) {
        int k0 = t * 32;
        uint32_t aoff = sbase + (uint32_t)(s * A_TILE) * 4u;
        uint32_t boff = sbase + (uint32_t)(2 * A_TILE + s * BD_TILE) * 4u;
#pragma unroll
        for (int i = 0; i < 4; i++) {
            int r = ar + i * 32;
            int m = m0 + r;
            int slot = base + ((m < cnt) ? m : (cnt - 1));
            cpa16(aoff + (uint32_t)(r * A_STRIDE + ac * 4) * 4u,
                  &g_hbuf[(size_t)slot * I_DIM + k0 + ac * 4]);
        }
#pragma unroll
        for (int i = 0; i < 4; i++) {
            int kr = br + i * 8;
            cpa16(boff + (uint32_t)(kr * BD_STRIDE + bc * 4) * 4u,
                  wb + (size_t)(k0 + kr) * H_DIM + bc * 4);
        }
        CP_COMMIT();
    };

    int wid = tid >> 5, lane = tid & 31;
    int wm = (wid & 3) * 32, wn = (wid >> 2) * 64;
    int gid = lane >> 2, tig = lane & 3;

    float cc[2][8][4];
#pragma unroll
    for (int i = 0; i < 2; i++)
#pragma unroll
        for (int j = 0; j < 8; j++)
#pragma unroll
            for (int q = 0; q < 4; q++) cc[i][j][q] = 0.0f;

    load_stage(0, 0);

    for (int t = 0; t < NT; t++) {
        if (t + 1 < NT) { load_stage(t + 1, (t + 1) & 1); CP_WAIT(1); }
        else            { CP_WAIT(0); }
        __syncthreads();

        const float* As = AsB + (t & 1) * A_TILE;
        const float* Bs = BsB + (t & 1) * BD_TILE;

#pragma unroll
        for (int kf = 0; kf < 32; kf += 8) {
            uint32_t a[2][4];
#pragma unroll
            for (int mf = 0; mf < 2; mf++) {
                int rb = wm + mf * 16;
                a[mf][0] = f2tf(As[(rb + gid) * A_STRIDE + kf + tig]);
                a[mf][1] = f2tf(As[(rb + gid + 8) * A_STRIDE + kf + tig]);
                a[mf][2] = f2tf(As[(rb + gid) * A_STRIDE + kf + tig + 4]);
                a[mf][3] = f2tf(As[(rb + gid + 8) * A_STRIDE + kf + tig + 4]);
            }
            uint32_t b[8][2];
#pragma unroll
            for (int nf = 0; nf < 8; nf++) {
                int cb = wn + nf * 8 + gid;
                b[nf][0] = f2tf(Bs[(kf + tig) * BD_STRIDE + cb]);
                b[nf][1] = f2tf(Bs[(kf + tig + 4) * BD_STRIDE + cb]);
            }
#pragma unroll
            for (int mf = 0; mf < 2; mf++)
#pragma unroll
                for (int nf = 0; nf < 8; nf++) mma8(cc[mf][nf], a[mf], b[nf]);
        }
        __syncthreads();
    }

#pragma unroll
    for (int mf = 0; mf < 2; mf++) {
        int r1 = wm + mf * 16 + gid;
        int r2 = r1 + 8;
        int m1 = m0 + r1, m2 = m0 + r2;
        float w1 = (m1 < cnt) ? g_slot_w[base + m1] : 0.0f;
        float w2 = (m2 < cnt) ? g_slot_w[base + m2] : 0.0f;
#pragma unroll
        for (int nf = 0; nf < 8; nf++) {
            int col = n0 + wn + nf * 8 + 2 * tig;
            if (m1 < cnt) {
                float2 v = make_float2(cc[mf][nf][0] * w1, cc[mf][nf][1] * w1);
                *(float2*)&g_dbuf[(size_t)(base + m1) * H_DIM + col] = v;
            }
            if (m2 < cnt) {
                float2 v = make_float2(cc[mf][nf][2] * w2, cc[mf][nf][3] * w2);
                *(float2*)&g_dbuf[(size_t)(base + m2) * H_DIM + col] = v;
            }
        }
    }
}

// ---------------- kernel 6: combine (float4) ----------------
__global__ void k_reduce(float* __restrict__ out) {
    int idx4 = blockIdx.x * blockDim.x + threadIdx.x;  // over T*H/4
    int t  = idx4 >> 9;           // / (H_DIM/4)
    int h4 = idx4 & 511;
    const int* ps = &g_pair2slot[t * TOPK];
    float4 s = make_float4(0.f, 0.f, 0.f, 0.f);
#pragma unroll
    for (int k = 0; k < TOPK; k++) {
        const float4 v = *(const float4*)&g_dbuf[(size_t)ps[k] * H_DIM + h4 * 4];
        s.x += v.x; s.y += v.y; s.z += v.z; s.w += v.w;
    }
    *(float4*)&out[(size_t)idx4 * 4] = s;
}

// ---------------- launch ----------------
extern "C" void kernel_launch(void* const* d_in, const int* in_sizes, int n_in,
                              void* d_out, int out_size) {
    const float* x  = (const float*)d_in[0];
    const float* gw = (const float*)d_in[1];
    const float* wg = (const float*)d_in[2];
    const float* wu = (const float*)d_in[3];
    const float* wd = (const float*)d_in[4];
    float* out = (float*)d_out;

    int write_ids = (out_size >= T_TOK * H_DIM + P_NUM) ? 1 : 0;

    const int smemA = (2 * A_TILE + 4 * BG_TILE) * 4;   // 71680 B
    const int smemB = (2 * A_TILE + 2 * BD_TILE) * 4;   // 70656 B
    cudaFuncSetAttribute(k_gemmA, cudaFuncAttributeMaxDynamicSharedMemorySize, smemA);
    cudaFuncSetAttribute(k_gemmB, cudaFuncAttributeMaxDynamicSharedMemorySize, smemB);

    k_zero<<<1, 32>>>();
    k_router<<<T_TOK / 8, 256>>>(x, gw, out, write_ids);
    k_scan<<<1, 32>>>();
    k_scatter<<<P_NUM / 256, 256>>>();

    dim3 ga(I_DIM / 64, T_TOK / 128, E_NUM);   // (16, 32, 32)
    k_gemmA<<<ga, 256, smemA>>>(x, wg, wu);

    dim3 gb(H_DIM / 128, T_TOK / 128, E_NUM);  // (16, 32, 32)
    k_gemmB<<<gb, 256, smemB>>>(wd);

    k_reduce<<<(T_TOK * H_DIM / 4) / 256, 256>>>(out);
}

// round 5
// speedup vs baseline: 1.1431x; 1.1431x over previous
#include <cuda_runtime.h>
#include <cstdint>
#include <math.h>

// Problem constants
#define T_TOK 4096
#define H_DIM 2048
#define E_NUM 32
#define I_DIM 1024
#define TOPK  8
#define P_NUM (T_TOK * TOPK)
#define W_ELEMS ((size_t)E_NUM * H_DIM * I_DIM)   // 67,108,864 per weight tensor

// ---------------- scratch ----------------
__device__ int   g_topk_ids[P_NUM];
__device__ float g_topk_w[P_NUM];
__device__ int   g_cnt[E_NUM];
__device__ int   g_pos[E_NUM];
__device__ int   g_off[E_NUM + 1];
__device__ int   g_slot_token[P_NUM];
__device__ float g_slot_w[P_NUM];
__device__ int   g_pair2slot[P_NUM];
__device__ float g_hbuf[(size_t)P_NUM * I_DIM];   // tf32-rounded activations
__device__ float g_dbuf[(size_t)P_NUM * H_DIM];
// tf32-pre-rounded operands (rounded ONCE, mainloops load raw bits)
__device__ float g_x_t[(size_t)T_TOK * H_DIM];
__device__ float g_wg_t[W_ELEMS];
__device__ float g_wu_t[W_ELEMS];
__device__ float g_wd_t[W_ELEMS];

// ---------------- helpers ----------------
__device__ __forceinline__ uint32_t f2tf(float f) {
    uint32_t u;
    asm("cvt.rna.tf32.f32 %0, %1;" : "=r"(u) : "f"(f));
    return u;
}

__device__ __forceinline__ void mma8(float c[4], const uint32_t a[4], const uint32_t b[2]) {
    asm volatile(
        "mma.sync.aligned.m16n8k8.row.col.f32.tf32.tf32.f32 "
        "{%0,%1,%2,%3}, {%4,%5,%6,%7}, {%8,%9}, {%0,%1,%2,%3};\n"
        : "+f"(c[0]), "+f"(c[1]), "+f"(c[2]), "+f"(c[3])
        : "r"(a[0]), "r"(a[1]), "r"(a[2]), "r"(a[3]), "r"(b[0]), "r"(b[1]));
}

__device__ __forceinline__ void cpa16(uint32_t saddr, const void* g) {
    asm volatile("cp.async.cg.shared.global [%0], [%1], 16;" :: "r"(saddr), "l"(g));
}
#define CP_COMMIT() asm volatile("cp.async.commit_group;")
#define CP_WAIT(N)  asm volatile("cp.async.wait_group %0;" :: "n"(N))

__device__ __forceinline__ float silu(float x) {
    return x * (1.0f / (1.0f + __expf(-x)));
}

// ---------------- kernel 0 ----------------
__global__ void k_zero() {
    if (threadIdx.x < E_NUM) g_cnt[threadIdx.x] = 0;
}

// ---------------- pre-round to tf32 (float4 grid) ----------------
__global__ void k_cvt(const float* __restrict__ src, float* __restrict__ dst) {
    size_t i = ((size_t)blockIdx.x * blockDim.x + threadIdx.x) * 4;
    float4 v = *(const float4*)(src + i);
    v.x = __uint_as_float(f2tf(v.x));
    v.y = __uint_as_float(f2tf(v.y));
    v.z = __uint_as_float(f2tf(v.z));
    v.w = __uint_as_float(f2tf(v.w));
    *(float4*)(dst + i) = v;
}

// ---------------- kernel 1: router ----------------
__global__ void k_router(const float* __restrict__ x, const float* __restrict__ gw,
                         float* __restrict__ out, int write_ids) {
    int warp = (blockIdx.x * blockDim.x + threadIdx.x) >> 5;
    int lane = threadIdx.x & 31;
    if (warp >= T_TOK) return;

    const float* xr = x + (size_t)warp * H_DIM;
    float acc = 0.0f;
#pragma unroll 8
    for (int h = 0; h < H_DIM; h++) acc += xr[h] * gw[h * E_NUM + lane];

    float m = acc;
#pragma unroll
    for (int o = 16; o; o >>= 1) m = fmaxf(m, __shfl_xor_sync(0xffffffffu, m, o));
    float p = expf(acc - m);
    float s = p;
#pragma unroll
    for (int o = 16; o; o >>= 1) s += __shfl_xor_sync(0xffffffffu, s, o);
    float score = p / s;

    float val = score;
    int   ids[TOPK];
    float ws[TOPK];
    float wsum = 0.0f;
#pragma unroll
    for (int j = 0; j < TOPK; j++) {
        float bv = val;
        int   bi = lane;
#pragma unroll
        for (int o = 16; o; o >>= 1) {
            float ov = __shfl_xor_sync(0xffffffffu, bv, o);
            int   oi = __shfl_xor_sync(0xffffffffu, bi, o);
            if (ov > bv || (ov == bv && oi < bi)) { bv = ov; bi = oi; }
        }
        ids[j] = bi; ws[j] = bv; wsum += bv;
        if (lane == bi) val = -1.0f;
    }

    if (lane == 0) {
        float inv = 1.0f / wsum;
#pragma unroll
        for (int j = 0; j < TOPK; j++) {
            g_topk_ids[warp * TOPK + j] = ids[j];
            g_topk_w[warp * TOPK + j]   = ws[j] * inv;
            atomicAdd(&g_cnt[ids[j]], 1);
            if (write_ids)
                out[(size_t)T_TOK * H_DIM + warp * TOPK + j] = (float)ids[j];
        }
    }
}

// ---------------- kernel 2/3 ----------------
__global__ void k_scan() {
    if (threadIdx.x == 0) {
        int acc = 0;
        for (int e = 0; e < E_NUM; e++) { g_off[e] = acc; g_pos[e] = acc; acc += g_cnt[e]; }
        g_off[E_NUM] = acc;
    }
}

__global__ void k_scatter() {
    int pp = blockIdx.x * blockDim.x + threadIdx.x;
    if (pp >= P_NUM) return;
    int e = g_topk_ids[pp];
    int slot = atomicAdd(&g_pos[e], 1);
    g_slot_token[slot] = pp >> 3;
    g_slot_w[slot]     = g_topk_w[pp];
    g_pair2slot[pp]    = slot;
}

// ================= kernel 4: fused gate+up GEMM + SwiGLU =================
// Block 128M x 64N, BK=32, 2-stage cp.async, 8 warps (4M x 2N), warp 32x32. 2 CTAs/SM.
#define A_STRIDE 36                 // 32 + pad; bank-unique for a-frags
#define A_TILE   (128 * A_STRIDE)   // 4608 floats / stage
#define BG_STRIDE 72                // bank-unique for b-frags (8*tig+gid)
#define BG_TILE  (32 * BG_STRIDE)   // 2304 floats / stage

__global__ __launch_bounds__(256, 2) void k_gemmA(const float* __restrict__ x,
                                                  const float* __restrict__ wgate,
                                                  const float* __restrict__ wup) {
    int e   = blockIdx.z;
    int cnt = g_cnt[e];
    int m0  = blockIdx.y * 128;
    if (m0 >= cnt) return;
    int n0   = blockIdx.x * 64;
    int base = g_off[e];
    int tid  = threadIdx.x;

    extern __shared__ float smem[];
    float* AsB = smem;
    float* BgB = smem + 2 * A_TILE;
    float* BuB = smem + 2 * A_TILE + 2 * BG_TILE;
    uint32_t sbase = (uint32_t)__cvta_generic_to_shared(smem);

    __shared__ int s_tok[128];
    if (tid < 128) {
        int m = m0 + tid;
        s_tok[tid] = g_slot_token[base + ((m < cnt) ? m : 0)];
    }
    __syncthreads();

    const float* wgb = wgate + (size_t)e * H_DIM * I_DIM + n0;
    const float* wub = wup   + (size_t)e * H_DIM * I_DIM + n0;

    int ac = tid & 7,  ar = tid >> 3;     // A: 8x16B chunks/row, 32 rows/pass
    int bc = tid & 15, br = tid >> 4;     // B: 16 chunks/row, 16 rows/pass

    const int NT = H_DIM / 32;  // 64

    auto load_stage = [&](int t, int s) {
        int k0 = t * 32;
        uint32_t aoff = sbase + (uint32_t)(s * A_TILE) * 4u;
        uint32_t goff = sbase + (uint32_t)(2 * A_TILE + s * BG_TILE) * 4u;
        uint32_t uoff = sbase + (uint32_t)(2 * A_TILE + 2 * BG_TILE + s * BG_TILE) * 4u;
#pragma unroll
        for (int i = 0; i < 4; i++) {
            int r = ar + i * 32;
            cpa16(aoff + (uint32_t)(r * A_STRIDE + ac * 4) * 4u,
                  x + (size_t)s_tok[r] * H_DIM + k0 + ac * 4);
        }
#pragma unroll
        for (int i = 0; i < 2; i++) {
            int kr = br + i * 16;
            uint32_t so = (uint32_t)(kr * BG_STRIDE + bc * 4) * 4u;
            cpa16(goff + so, wgb + (size_t)(k0 + kr) * I_DIM + bc * 4);
            cpa16(uoff + so, wub + (size_t)(k0 + kr) * I_DIM + bc * 4);
        }
        CP_COMMIT();
    };

    int wid = tid >> 5, lane = tid & 31;
    int wm = (wid & 3) * 32, wn = (wid >> 2) * 32;
    int gid = lane >> 2, tig = lane & 3;

    float cg[2][4][4], cu[2][4][4];
#pragma unroll
    for (int i = 0; i < 2; i++)
#pragma unroll
        for (int j = 0; j < 4; j++)
#pragma unroll
            for (int q = 0; q < 4; q++) { cg[i][j][q] = 0.0f; cu[i][j][q] = 0.0f; }

    load_stage(0, 0);

    for (int t = 0; t < NT; t++) {
        if (t + 1 < NT) { load_stage(t + 1, (t + 1) & 1); CP_WAIT(1); }
        else            { CP_WAIT(0); }
        __syncthreads();

        const float* As = AsB + (t & 1) * A_TILE;
        const float* Bg = BgB + (t & 1) * BG_TILE;
        const float* Bu = BuB + (t & 1) * BG_TILE;

#pragma unroll
        for (int kf = 0; kf < 32; kf += 8) {
            uint32_t a[2][4];
#pragma unroll
            for (int mf = 0; mf < 2; mf++) {
                int rb = wm + mf * 16;
                a[mf][0] = __float_as_uint(As[(rb + gid) * A_STRIDE + kf + tig]);
                a[mf][1] = __float_as_uint(As[(rb + gid + 8) * A_STRIDE + kf + tig]);
                a[mf][2] = __float_as_uint(As[(rb + gid) * A_STRIDE + kf + tig + 4]);
                a[mf][3] = __float_as_uint(As[(rb + gid + 8) * A_STRIDE + kf + tig + 4]);
            }
            uint32_t bg[4][2], bu[4][2];
#pragma unroll
            for (int nf = 0; nf < 4; nf++) {
                int cb = wn + nf * 8 + gid;
                bg[nf][0] = __float_as_uint(Bg[(kf + tig) * BG_STRIDE + cb]);
                bg[nf][1] = __float_as_uint(Bg[(kf + tig + 4) * BG_STRIDE + cb]);
                bu[nf][0] = __float_as_uint(Bu[(kf + tig) * BG_STRIDE + cb]);
                bu[nf][1] = __float_as_uint(Bu[(kf + tig + 4) * BG_STRIDE + cb]);
            }
#pragma unroll
            for (int mf = 0; mf < 2; mf++)
#pragma unroll
                for (int nf = 0; nf < 4; nf++) {
                    mma8(cg[mf][nf], a[mf], bg[nf]);
                    mma8(cu[mf][nf], a[mf], bu[nf]);
                }
        }
        __syncthreads();
    }

    // epilogue: h = silu(g)*u, tf32-rounded so gemmB loads raw bits
#pragma unroll
    for (int mf = 0; mf < 2; mf++)
#pragma unroll
        for (int nf = 0; nf < 4; nf++) {
            int col = n0 + wn + nf * 8 + 2 * tig;
            int r1 = wm + mf * 16 + gid;
            int r2 = r1 + 8;
            int m1 = m0 + r1, m2 = m0 + r2;
            if (m1 < cnt) {
                float2 v = make_float2(
                    __uint_as_float(f2tf(silu(cg[mf][nf][0]) * cu[mf][nf][0])),
                    __uint_as_float(f2tf(silu(cg[mf][nf][1]) * cu[mf][nf][1])));
                *(float2*)&g_hbuf[(size_t)(base + m1) * I_DIM + col] = v;
            }
            if (m2 < cnt) {
                float2 v = make_float2(
                    __uint_as_float(f2tf(silu(cg[mf][nf][2]) * cu[mf][nf][2])),
                    __uint_as_float(f2tf(silu(cg[mf][nf][3]) * cu[mf][nf][3])));
                *(float2*)&g_dbuf[0] = *(float2*)&g_dbuf[0], // no-op guard never taken
                *(float2*)&g_hbuf[(size_t)(base + m2) * I_DIM + col] = v;
            }
        }
}

// ================= kernel 5: down GEMM (weighted) =================
// Block 128M x 128N, BK=32, 2-stage cp.async, 8 warps (4M x 2N), warp 32x64. 2 CTAs/SM.
#define BD_STRIDE 136
#define BD_TILE   (32 * BD_STRIDE)   // 4352 floats / stage

__global__ __launch_bounds__(256, 2) void k_gemmB(const float* __restrict__ wdown) {
    int e   = blockIdx.z;
    int cnt = g_cnt[e];
    int m0  = blockIdx.y * 128;
    if (m0 >= cnt) return;
    int n0   = blockIdx.x * 128;
    int base = g_off[e];
    int tid  = threadIdx.x;

    extern __shared__ float smem[];
    float* AsB = smem;
    float* BsB = smem + 2 * A_TILE;
    uint32_t sbase = (uint32_t)__cvta_generic_to_shared(smem);

    const float* wb = wdown + (size_t)e * I_DIM * H_DIM + n0;

    int ac = tid & 7,  ar = tid >> 3;
    int bc = tid & 31, br = tid >> 5;

    const int NT = I_DIM / 32;  // 32

    auto load_stage = [&](int t, int s) {
        int k0 = t * 32;
        uint32_t aoff = sbase + (uint32_t)(s * A_TILE) * 4u;
        uint32_t boff = sbase + (uint32_t)(2 * A_TILE + s * BD_TILE) * 4u;
#pragma unroll
        for (int i = 0; i < 4; i++) {
            int r = ar + i * 32;
            int m = m0 + r;
            int slot = base + ((m < cnt) ? m : (cnt - 1));
            cpa16(aoff + (uint32_t)(r * A_STRIDE + ac * 4) * 4u,
                  &g_hbuf[(size_t)slot * I_DIM + k0 + ac * 4]);
        }
#pragma unroll
        for (int i = 0; i < 4; i++) {
            int kr = br + i * 8;
            cpa16(boff + (uint32_t)(kr * BD_STRIDE + bc * 4) * 4u,
                  wb + (size_t)(k0 + kr) * H_DIM + bc * 4);
        }
        CP_COMMIT();
    };

    int wid = tid >> 5, lane = tid & 31;
    int wm = (wid & 3) * 32, wn = (wid >> 2) * 64;
    int gid = lane >> 2, tig = lane & 3;

    float cc[2][8][4];
#pragma unroll
    for (int i = 0; i < 2; i++)
#pragma unroll
        for (int j = 0; j < 8; j++)
#pragma unroll
            for (int q = 0; q < 4; q++) cc[i][j][q] = 0.0f;

    load_stage(0, 0);

    for (int t = 0; t < NT; t++) {
        if (t + 1 < NT) { load_stage(t + 1, (t + 1) & 1); CP_WAIT(1); }
        else            { CP_WAIT(0); }
        __syncthreads();

        const float* As = AsB + (t & 1) * A_TILE;
        const float* Bs = BsB + (t & 1) * BD_TILE;

#pragma unroll
        for (int kf = 0; kf < 32; kf += 8) {
            uint32_t a[2][4];
#pragma unroll
            for (int mf = 0; mf < 2; mf++) {
                int rb = wm + mf * 16;
                a[mf][0] = __float_as_uint(As[(rb + gid) * A_STRIDE + kf + tig]);
                a[mf][1] = __float_as_uint(As[(rb + gid + 8) * A_STRIDE + kf + tig]);
                a[mf][2] = __float_as_uint(As[(rb + gid) * A_STRIDE + kf + tig + 4]);
                a[mf][3] = __float_as_uint(As[(rb + gid + 8) * A_STRIDE + kf + tig + 4]);
            }
            uint32_t b[8][2];
#pragma unroll
            for (int nf = 0; nf < 8; nf++) {
                int cb = wn + nf * 8 + gid;
                b[nf][0] = __float_as_uint(Bs[(kf + tig) * BD_STRIDE + cb]);
                b[nf][1] = __float_as_uint(Bs[(kf + tig + 4) * BD_STRIDE + cb]);
            }
#pragma unroll
            for (int mf = 0; mf < 2; mf++)
#pragma unroll
                for (int nf = 0; nf < 8; nf++) mma8(cc[mf][nf], a[mf], b[nf]);
        }
        __syncthreads();
    }

#pragma unroll
    for (int mf = 0; mf < 2; mf++) {
        int r1 = wm + mf * 16 + gid;
        int r2 = r1 + 8;
        int m1 = m0 + r1, m2 = m0 + r2;
        float w1 = (m1 < cnt) ? g_slot_w[base + m1] : 0.0f;
        float w2 = (m2 < cnt) ? g_slot_w[base + m2] : 0.0f;
#pragma unroll
        for (int nf = 0; nf < 8; nf++) {
            int col = n0 + wn + nf * 8 + 2 * tig;
            if (m1 < cnt) {
                float2 v = make_float2(cc[mf][nf][0] * w1, cc[mf][nf][1] * w1);
                *(float2*)&g_dbuf[(size_t)(base + m1) * H_DIM + col] = v;
            }
            if (m2 < cnt) {
                float2 v = make_float2(cc[mf][nf][2] * w2, cc[mf][nf][3] * w2);
                *(float2*)&g_dbuf[(size_t)(base + m2) * H_DIM + col] = v;
            }
        }
    }
}

// ---------------- kernel 6: combine (float4) ----------------
__global__ void k_reduce(float* __restrict__ out) {
    int idx4 = blockIdx.x * blockDim.x + threadIdx.x;
    int t  = idx4 >> 9;
    int h4 = idx4 & 511;
    const int* ps = &g_pair2slot[t * TOPK];
    float4 s = make_float4(0.f, 0.f, 0.f, 0.f);
#pragma unroll
    for (int k = 0; k < TOPK; k++) {
        const float4 v = *(const float4*)&g_dbuf[(size_t)ps[k] * H_DIM + h4 * 4];
        s.x += v.x; s.y += v.y; s.z += v.z; s.w += v.w;
    }
    *(float4*)&out[(size_t)idx4 * 4] = s;
}

// ---------------- launch ----------------
extern "C" void kernel_launch(void* const* d_in, const int* in_sizes, int n_in,
                              void* d_out, int out_size) {
    const float* x  = (const float*)d_in[0];
    const float* gw = (const float*)d_in[1];
    const float* wg = (const float*)d_in[2];
    const float* wu = (const float*)d_in[3];
    const float* wd = (const float*)d_in[4];
    float* out = (float*)d_out;

    int write_ids = (out_size >= T_TOK * H_DIM + P_NUM) ? 1 : 0;

    const int smemA = (2 * A_TILE + 4 * BG_TILE) * 4;   // 73728 B
    const int smemB = (2 * A_TILE + 2 * BD_TILE) * 4;   // 71680 B
    static bool attr_set = false;
    cudaFuncSetAttribute(k_gemmA, cudaFuncAttributeMaxDynamicSharedMemorySize, smemA);
    cudaFuncSetAttribute(k_gemmB, cudaFuncAttributeMaxDynamicSharedMemorySize, smemB);
    (void)attr_set;

    k_zero<<<1, 32>>>();
    k_router<<<T_TOK / 8, 256>>>(x, gw, out, write_ids);
    k_scan<<<1, 32>>>();
    k_scatter<<<P_NUM / 256, 256>>>();

    // pre-round all GEMM operands to tf32 (once per call)
    float* wg_t; float* wu_t; float* wd_t; float* x_t;
    cudaGetSymbolAddress((void**)&wg_t, g_wg_t);
    cudaGetSymbolAddress((void**)&wu_t, g_wu_t);
    cudaGetSymbolAddress((void**)&wd_t, g_wd_t);
    cudaGetSymbolAddress((void**)&x_t,  g_x_t);
    k_cvt<<<(int)(W_ELEMS / 4 / 256), 256>>>(wg, wg_t);
    k_cvt<<<(int)(W_ELEMS / 4 / 256), 256>>>(wu, wu_t);
    k_cvt<<<(int)(W_ELEMS / 4 / 256), 256>>>(wd, wd_t);
    k_cvt<<<(T_TOK * H_DIM / 4) / 256, 256>>>(x, x_t);

    dim3 ga(I_DIM / 64, T_TOK / 128, E_NUM);   // (16, 32, 32)
    k_gemmA<<<ga, 256, smemA>>>(x_t, wg_t, wu_t);

    dim3 gb(H_DIM / 128, T_TOK / 128, E_NUM);  // (16, 32, 32)
    k_gemmB<<<gb, 256, smemB>>>(wd_t);

    k_reduce<<<(T_TOK * H_DIM / 4) / 256, 256>>>(out);
}

// round 6
// speedup vs baseline: 1.1738x; 1.0269x over previous
#include <cuda_runtime.h>
#include <cstdint>
#include <math.h>

// Problem constants
#define T_TOK 4096
#define H_DIM 2048
#define E_NUM 32
#define I_DIM 1024
#define TOPK  8
#define P_NUM (T_TOK * TOPK)
#define W_ELEMS ((size_t)E_NUM * H_DIM * I_DIM)

// ---------------- scratch ----------------
__device__ int   g_topk_ids[P_NUM];
__device__ float g_topk_w[P_NUM];
__device__ int   g_cnt[E_NUM];
__device__ int   g_pos[E_NUM];
__device__ int   g_off[E_NUM + 1];
__device__ int   g_slot_token[P_NUM];
__device__ float g_slot_w[P_NUM];
__device__ int   g_pair2slot[P_NUM];
__device__ float g_hbuf[(size_t)P_NUM * I_DIM];   // tf32-rounded activations
__device__ float g_dbuf[(size_t)P_NUM * H_DIM];
// tf32-pre-rounded operands
__device__ float g_x_t[(size_t)T_TOK * H_DIM];
__device__ float g_wg_t[W_ELEMS];
__device__ float g_wu_t[W_ELEMS];
__device__ float g_wd_t[W_ELEMS];

// ---------------- helpers ----------------
__device__ __forceinline__ uint32_t f2tf(float f) {
    uint32_t u;
    asm("cvt.rna.tf32.f32 %0, %1;" : "=r"(u) : "f"(f));
    return u;
}

__device__ __forceinline__ void mma8(float c[4], const uint32_t a[4], const uint32_t b[2]) {
    asm volatile(
        "mma.sync.aligned.m16n8k8.row.col.f32.tf32.tf32.f32 "
        "{%0,%1,%2,%3}, {%4,%5,%6,%7}, {%8,%9}, {%0,%1,%2,%3};\n"
        : "+f"(c[0]), "+f"(c[1]), "+f"(c[2]), "+f"(c[3])
        : "r"(a[0]), "r"(a[1]), "r"(a[2]), "r"(a[3]), "r"(b[0]), "r"(b[1]));
}

__device__ __forceinline__ void cpa16(uint32_t saddr, const void* g) {
    asm volatile("cp.async.cg.shared.global [%0], [%1], 16;" :: "r"(saddr), "l"(g));
}
#define CP_COMMIT() asm volatile("cp.async.commit_group;")
#define CP_WAIT(N)  asm volatile("cp.async.wait_group %0;" :: "n"(N))

__device__ __forceinline__ float silu(float x) {
    return x * (1.0f / (1.0f + __expf(-x)));
}

// ---------------- kernel 0 ----------------
__global__ void k_zero() {
    if (threadIdx.x < E_NUM) g_cnt[threadIdx.x] = 0;
}

// ---------------- pre-round to tf32 ----------------
__global__ void k_cvt(const float* __restrict__ src, float* __restrict__ dst) {
    size_t i = ((size_t)blockIdx.x * blockDim.x + threadIdx.x) * 4;
    float4 v = *(const float4*)(src + i);
    v.x = __uint_as_float(f2tf(v.x));
    v.y = __uint_as_float(f2tf(v.y));
    v.z = __uint_as_float(f2tf(v.z));
    v.w = __uint_as_float(f2tf(v.w));
    *(float4*)(dst + i) = v;
}

// ---------------- kernel 1: router (smem-tiled gw) ----------------
// 8 tokens/block (8 warps); gw staged through smem in 64-row chunks.
__global__ __launch_bounds__(256) void k_router(const float* __restrict__ x,
                                                const float* __restrict__ gw,
                                                float* __restrict__ out, int write_ids) {
    __shared__ float s_gw[64 * E_NUM];  // 8 KB
    int tid  = threadIdx.x;
    int wid  = tid >> 5, lane = tid & 31;
    int tok  = blockIdx.x * 8 + wid;

    const float* xr = x + (size_t)tok * H_DIM;
    float acc = 0.0f;
    for (int h0 = 0; h0 < H_DIM; h0 += 64) {
#pragma unroll
        for (int i = 0; i < 8; i++) s_gw[tid + i * 256] = gw[h0 * E_NUM + tid + i * 256];
        __syncthreads();
#pragma unroll 16
        for (int hh = 0; hh < 64; hh++) acc += xr[h0 + hh] * s_gw[hh * E_NUM + lane];
        __syncthreads();
    }

    float m = acc;
#pragma unroll
    for (int o = 16; o; o >>= 1) m = fmaxf(m, __shfl_xor_sync(0xffffffffu, m, o));
    float p = expf(acc - m);
    float s = p;
#pragma unroll
    for (int o = 16; o; o >>= 1) s += __shfl_xor_sync(0xffffffffu, s, o);
    float score = p / s;

    float val = score;
    int   ids[TOPK];
    float ws[TOPK];
    float wsum = 0.0f;
#pragma unroll
    for (int j = 0; j < TOPK; j++) {
        float bv = val;
        int   bi = lane;
#pragma unroll
        for (int o = 16; o; o >>= 1) {
            float ov = __shfl_xor_sync(0xffffffffu, bv, o);
            int   oi = __shfl_xor_sync(0xffffffffu, bi, o);
            if (ov > bv || (ov == bv && oi < bi)) { bv = ov; bi = oi; }
        }
        ids[j] = bi; ws[j] = bv; wsum += bv;
        if (lane == bi) val = -1.0f;
    }

    if (lane == 0) {
        float inv = 1.0f / wsum;
#pragma unroll
        for (int j = 0; j < TOPK; j++) {
            g_topk_ids[tok * TOPK + j] = ids[j];
            g_topk_w[tok * TOPK + j]   = ws[j] * inv;
            atomicAdd(&g_cnt[ids[j]], 1);
            if (write_ids)
                out[(size_t)T_TOK * H_DIM + tok * TOPK + j] = (float)ids[j];
        }
    }
}

// ---------------- kernel 2/3 ----------------
__global__ void k_scan() {
    if (threadIdx.x == 0) {
        int acc = 0;
        for (int e = 0; e < E_NUM; e++) { g_off[e] = acc; g_pos[e] = acc; acc += g_cnt[e]; }
        g_off[E_NUM] = acc;
    }
}

__global__ void k_scatter() {
    int pp = blockIdx.x * blockDim.x + threadIdx.x;
    if (pp >= P_NUM) return;
    int e = g_topk_ids[pp];
    int slot = atomicAdd(&g_pos[e], 1);
    g_slot_token[slot] = pp >> 3;
    g_slot_w[slot]     = g_topk_w[pp];
    g_pair2slot[pp]    = slot;
}

// ================= kernel 4: fused gate+up GEMM + SwiGLU =================
// Block 128M x 64N, BK=32, 3-stage cp.async, ONE sync/K-tile, 8 warps, 2 CTAs/SM.
#define A_STRIDE 36
#define A_TILE   (128 * A_STRIDE)   // 4608 floats / stage
#define BG_STRIDE 72
#define BG_TILE  (32 * BG_STRIDE)   // 2304 floats / stage

__global__ __launch_bounds__(256, 2) void k_gemmA(const float* __restrict__ x,
                                                  const float* __restrict__ wgate,
                                                  const float* __restrict__ wup) {
    int e   = blockIdx.z;
    int cnt = g_cnt[e];
    int m0  = blockIdx.y * 128;
    if (m0 >= cnt) return;
    int n0   = blockIdx.x * 64;
    int base = g_off[e];
    int tid  = threadIdx.x;

    extern __shared__ float smem[];
    float* AsB = smem;                       // 3 stages
    float* BgB = smem + 3 * A_TILE;          // 3 stages
    float* BuB = smem + 3 * A_TILE + 3 * BG_TILE;
    uint32_t sbase = (uint32_t)__cvta_generic_to_shared(smem);

    __shared__ int s_tok[128];
    if (tid < 128) {
        int m = m0 + tid;
        s_tok[tid] = g_slot_token[base + ((m < cnt) ? m : 0)];
    }
    __syncthreads();

    const float* wgb = wgate + (size_t)e * H_DIM * I_DIM + n0;
    const float* wub = wup   + (size_t)e * H_DIM * I_DIM + n0;

    int ac = tid & 7,  ar = tid >> 3;
    int bc = tid & 15, br = tid >> 4;

    const int NT = H_DIM / 32;  // 64

    auto load_stage = [&](int t, int s) {
        int k0 = t * 32;
        uint32_t aoff = sbase + (uint32_t)(s * A_TILE) * 4u;
        uint32_t goff = sbase + (uint32_t)(3 * A_TILE + s * BG_TILE) * 4u;
        uint32_t uoff = sbase + (uint32_t)(3 * A_TILE + 3 * BG_TILE + s * BG_TILE) * 4u;
#pragma unroll
        for (int i = 0; i < 4; i++) {
            int r = ar + i * 32;
            cpa16(aoff + (uint32_t)(r * A_STRIDE + ac * 4) * 4u,
                  x + (size_t)s_tok[r] * H_DIM + k0 + ac * 4);
        }
#pragma unroll
        for (int i = 0; i < 2; i++) {
            int kr = br + i * 16;
            uint32_t so = (uint32_t)(kr * BG_STRIDE + bc * 4) * 4u;
            cpa16(goff + so, wgb + (size_t)(k0 + kr) * I_DIM + bc * 4);
            cpa16(uoff + so, wub + (size_t)(k0 + kr) * I_DIM + bc * 4);
        }
        CP_COMMIT();
    };

    int wid = tid >> 5, lane = tid & 31;
    int wm = (wid & 3) * 32, wn = (wid >> 2) * 32;
    int gid = lane >> 2, tig = lane & 3;

    float cg[2][4][4], cu[2][4][4];
#pragma unroll
    for (int i = 0; i < 2; i++)
#pragma unroll
        for (int j = 0; j < 4; j++)
#pragma unroll
            for (int q = 0; q < 4; q++) { cg[i][j][q] = 0.0f; cu[i][j][q] = 0.0f; }

    load_stage(0, 0);
    load_stage(1, 1);

    int sl = 2, sc = 0;  // slot-to-load, slot-to-compute
    for (int t = 0; t < NT; t++) {
        if (t + 1 < NT) { CP_WAIT(1); } else { CP_WAIT(0); }
        __syncthreads();
        if (t + 2 < NT) {
            load_stage(t + 2, sl);
            if (++sl == 3) sl = 0;
        }

        const float* As = AsB + sc * A_TILE;
        const float* Bg = BgB + sc * BG_TILE;
        const float* Bu = BuB + sc * BG_TILE;
        if (++sc == 3) sc = 0;

#pragma unroll
        for (int kf = 0; kf < 32; kf += 8) {
            uint32_t a[2][4];
#pragma unroll
            for (int mf = 0; mf < 2; mf++) {
                int rb = wm + mf * 16;
                a[mf][0] = __float_as_uint(As[(rb + gid) * A_STRIDE + kf + tig]);
                a[mf][1] = __float_as_uint(As[(rb + gid + 8) * A_STRIDE + kf + tig]);
                a[mf][2] = __float_as_uint(As[(rb + gid) * A_STRIDE + kf + tig + 4]);
                a[mf][3] = __float_as_uint(As[(rb + gid + 8) * A_STRIDE + kf + tig + 4]);
            }
            uint32_t bg[4][2], bu[4][2];
#pragma unroll
            for (int nf = 0; nf < 4; nf++) {
                int cb = wn + nf * 8 + gid;
                bg[nf][0] = __float_as_uint(Bg[(kf + tig) * BG_STRIDE + cb]);
                bg[nf][1] = __float_as_uint(Bg[(kf + tig + 4) * BG_STRIDE + cb]);
                bu[nf][0] = __float_as_uint(Bu[(kf + tig) * BG_STRIDE + cb]);
                bu[nf][1] = __float_as_uint(Bu[(kf + tig + 4) * BG_STRIDE + cb]);
            }
#pragma unroll
            for (int mf = 0; mf < 2; mf++)
#pragma unroll
                for (int nf = 0; nf < 4; nf++) {
                    mma8(cg[mf][nf], a[mf], bg[nf]);
                    mma8(cu[mf][nf], a[mf], bu[nf]);
                }
        }
    }

    // epilogue: h = silu(g)*u, tf32-rounded
#pragma unroll
    for (int mf = 0; mf < 2; mf++)
#pragma unroll
        for (int nf = 0; nf < 4; nf++) {
            int col = n0 + wn + nf * 8 + 2 * tig;
            int r1 = wm + mf * 16 + gid;
            int r2 = r1 + 8;
            int m1 = m0 + r1, m2 = m0 + r2;
            if (m1 < cnt) {
                float2 v = make_float2(
                    __uint_as_float(f2tf(silu(cg[mf][nf][0]) * cu[mf][nf][0])),
                    __uint_as_float(f2tf(silu(cg[mf][nf][1]) * cu[mf][nf][1])));
                *(float2*)&g_hbuf[(size_t)(base + m1) * I_DIM + col] = v;
            }
            if (m2 < cnt) {
                float2 v = make_float2(
                    __uint_as_float(f2tf(silu(cg[mf][nf][2]) * cu[mf][nf][2])),
                    __uint_as_float(f2tf(silu(cg[mf][nf][3]) * cu[mf][nf][3])));
                *(float2*)&g_hbuf[(size_t)(base + m2) * I_DIM + col] = v;
            }
        }
}

// ================= kernel 5: down GEMM (weighted) =================
// Block 128M x 128N, BK=32, 3-stage cp.async, ONE sync/K-tile, 8 warps, 2 CTAs/SM.
#define BD_STRIDE 136
#define BD_TILE   (32 * BD_STRIDE)   // 4352 floats / stage

__global__ __launch_bounds__(256, 2) void k_gemmB(const float* __restrict__ wdown) {
    int e   = blockIdx.z;
    int cnt = g_cnt[e];
    int m0  = blockIdx.y * 128;
    if (m0 >= cnt) return;
    int n0   = blockIdx.x * 128;
    int base = g_off[e];
    int tid  = threadIdx.x;

    extern __shared__ float smem[];
    float* AsB = smem;
    float* BsB = smem + 3 * A_TILE;
    uint32_t sbase = (uint32_t)__cvta_generic_to_shared(smem);

    const float* wb = wdown + (size_t)e * I_DIM * H_DIM + n0;

    int ac = tid & 7,  ar = tid >> 3;
    int bc = tid & 31, br = tid >> 5;

    const int NT = I_DIM / 32;  // 32

    auto load_stage = [&](int t, int s) {
        int k0 = t * 32;
        uint32_t aoff = sbase + (uint32_t)(s * A_TILE) * 4u;
        uint32_t boff = sbase + (uint32_t)(3 * A_TILE + s * BD_TILE) * 4u;
#pragma unroll
        for (int i = 0; i < 4; i++) {
            int r = ar + i * 32;
            int m = m0 + r;
            int slot = base + ((m < cnt) ? m : (cnt - 1));
            cpa16(aoff + (uint32_t)(r * A_STRIDE + ac * 4) * 4u,
                  &g_hbuf[(size_t)slot * I_DIM + k0 + ac * 4]);
        }
#pragma unroll
        for (int i = 0; i < 4; i++) {
            int kr = br + i * 8;
            cpa16(boff + (uint32_t)(kr * BD_STRIDE + bc * 4) * 4u,
                  wb + (size_t)(k0 + kr) * H_DIM + bc * 4);
        }
        CP_COMMIT();
    };

    int wid = tid >> 5, lane = tid & 31;
    int wm = (wid & 3) * 32, wn = (wid >> 2) * 64;
    int gid = lane >> 2, tig = lane & 3;

    float cc[2][8][4];
#pragma unroll
    for (int i = 0; i < 2; i++)
#pragma unroll
        for (int j = 0; j < 8; j++)
#pragma unroll
            for (int q = 0; q < 4; q++) cc[i][j][q] = 0.0f;

    load_stage(0, 0);
    load_stage(1, 1);

    int sl = 2, sc = 0;
    for (int t = 0; t < NT; t++) {
        if (t + 1 < NT) { CP_WAIT(1); } else { CP_WAIT(0); }
        __syncthreads();
        if (t + 2 < NT) {
            load_stage(t + 2, sl);
            if (++sl == 3) sl = 0;
        }

        const float* As = AsB + sc * A_TILE;
        const float* Bs = BsB + sc * BD_TILE;
        if (++sc == 3) sc = 0;

#pragma unroll
        for (int kf = 0; kf < 32; kf += 8) {
            uint32_t a[2][4];
#pragma unroll
            for (int mf = 0; mf < 2; mf++) {
                int rb = wm + mf * 16;
                a[mf][0] = __float_as_uint(As[(rb + gid) * A_STRIDE + kf + tig]);
                a[mf][1] = __float_as_uint(As[(rb + gid + 8) * A_STRIDE + kf + tig]);
                a[mf][2] = __float_as_uint(As[(rb + gid) * A_STRIDE + kf + tig + 4]);
                a[mf][3] = __float_as_uint(As[(rb + gid + 8) * A_STRIDE + kf + tig + 4]);
            }
            uint32_t b[8][2];
#pragma unroll
            for (int nf = 0; nf < 8; nf++) {
                int cb = wn + nf * 8 + gid;
                b[nf][0] = __float_as_uint(Bs[(kf + tig) * BD_STRIDE + cb]);
                b[nf][1] = __float_as_uint(Bs[(kf + tig + 4) * BD_STRIDE + cb]);
            }
#pragma unroll
            for (int mf = 0; mf < 2; mf++)
#pragma unroll
                for (int nf = 0; nf < 8; nf++) mma8(cc[mf][nf], a[mf], b[nf]);
        }
    }

#pragma unroll
    for (int mf = 0; mf < 2; mf++) {
        int r1 = wm + mf * 16 + gid;
        int r2 = r1 + 8;
        int m1 = m0 + r1, m2 = m0 + r2;
        float w1 = (m1 < cnt) ? g_slot_w[base + m1] : 0.0f;
        float w2 = (m2 < cnt) ? g_slot_w[base + m2] : 0.0f;
#pragma unroll
        for (int nf = 0; nf < 8; nf++) {
            int col = n0 + wn + nf * 8 + 2 * tig;
            if (m1 < cnt) {
                float2 v = make_float2(cc[mf][nf][0] * w1, cc[mf][nf][1] * w1);
                *(float2*)&g_dbuf[(size_t)(base + m1) * H_DIM + col] = v;
            }
            if (m2 < cnt) {
                float2 v = make_float2(cc[mf][nf][2] * w2, cc[mf][nf][3] * w2);
                *(float2*)&g_dbuf[(size_t)(base + m2) * H_DIM + col] = v;
            }
        }
    }
}

// ---------------- kernel 6: combine ----------------
__global__ void k_reduce(float* __restrict__ out) {
    int idx4 = blockIdx.x * blockDim.x + threadIdx.x;
    int t  = idx4 >> 9;
    int h4 = idx4 & 511;
    const int* ps = &g_pair2slot[t * TOPK];
    float4 s = make_float4(0.f, 0.f, 0.f, 0.f);
#pragma unroll
    for (int k = 0; k < TOPK; k++) {
        const float4 v = *(const float4*)&g_dbuf[(size_t)ps[k] * H_DIM + h4 * 4];
        s.x += v.x; s.y += v.y; s.z += v.z; s.w += v.w;
    }
    *(float4*)&out[(size_t)idx4 * 4] = s;
}

// ---------------- launch ----------------
extern "C" void kernel_launch(void* const* d_in, const int* in_sizes, int n_in,
                              void* d_out, int out_size) {
    const float* x  = (const float*)d_in[0];
    const float* gw = (const float*)d_in[1];
    const float* wg = (const float*)d_in[2];
    const float* wu = (const float*)d_in[3];
    const float* wd = (const float*)d_in[4];
    float* out = (float*)d_out;

    int write_ids = (out_size >= T_TOK * H_DIM + P_NUM) ? 1 : 0;

    const int smemA = (3 * A_TILE + 6 * BG_TILE) * 4;   // 110592 B
    const int smemB = (3 * A_TILE + 3 * BD_TILE) * 4;   // 107520 B
    cudaFuncSetAttribute(k_gemmA, cudaFuncAttributeMaxDynamicSharedMemorySize, smemA);
    cudaFuncSetAttribute(k_gemmB, cudaFuncAttributeMaxDynamicSharedMemorySize, smemB);

    k_zero<<<1, 32>>>();
    k_router<<<T_TOK / 8, 256>>>(x, gw, out, write_ids);
    k_scan<<<1, 32>>>();
    k_scatter<<<P_NUM / 256, 256>>>();

    float* wg_t; float* wu_t; float* wd_t; float* x_t;
    cudaGetSymbolAddress((void**)&wg_t, g_wg_t);
    cudaGetSymbolAddress((void**)&wu_t, g_wu_t);
    cudaGetSymbolAddress((void**)&wd_t, g_wd_t);
    cudaGetSymbolAddress((void**)&x_t,  g_x_t);
    k_cvt<<<(int)(W_ELEMS / 4 / 256), 256>>>(wg, wg_t);
    k_cvt<<<(int)(W_ELEMS / 4 / 256), 256>>>(wu, wu_t);
    k_cvt<<<(int)(W_ELEMS / 4 / 256), 256>>>(wd, wd_t);
    k_cvt<<<(T_TOK * H_DIM / 4) / 256, 256>>>(x, x_t);

    dim3 ga(I_DIM / 64, T_TOK / 128, E_NUM);   // (16, 32, 32)
    k_gemmA<<<ga, 256, smemA>>>(x_t, wg_t, wu_t);

    dim3 gb(H_DIM / 128, T_TOK / 128, E_NUM);  // (16, 32, 32)
    k_gemmB<<<gb, 256, smemB>>>(wd_t);

    k_reduce<<<(T_TOK * H_DIM / 4) / 256, 256>>>(out);
}

// round 8
// speedup vs baseline: 1.1834x; 1.0082x over previous
#include <cuda_runtime.h>
#include <cstdint>
#include <math.h>

// Problem constants
#define T_TOK 4096
#define H_DIM 2048
#define E_NUM 32
#define I_DIM 1024
#define TOPK  8
#define P_NUM (T_TOK * TOPK)
#define W_ELEMS ((size_t)E_NUM * H_DIM * I_DIM)

// ---------------- scratch ----------------
__device__ int   g_topk_ids[P_NUM];
__device__ float g_topk_w[P_NUM];
__device__ int   g_cnt[E_NUM];
__device__ int   g_pos[E_NUM];
__device__ int   g_off[E_NUM + 1];
__device__ int   g_slot_token[P_NUM];
__device__ float g_slot_w[P_NUM];
__device__ int   g_pair2slot[P_NUM];
__device__ float g_hbuf[(size_t)P_NUM * I_DIM];   // tf32-rounded activations
__device__ float g_dbuf[(size_t)P_NUM * H_DIM];
// tf32-pre-rounded operands
__device__ float g_x_t[(size_t)T_TOK * H_DIM];
__device__ float g_wg_t[W_ELEMS];
__device__ float g_wu_t[W_ELEMS];
__device__ float g_wd_t[W_ELEMS];

// ---------------- helpers ----------------
__device__ __forceinline__ uint32_t f2tf(float f) {
    uint32_t u;
    asm("cvt.rna.tf32.f32 %0, %1;" : "=r"(u) : "f"(f));
    return u;
}

__device__ __forceinline__ void mma8(float c[4], const uint32_t a[4], const uint32_t b[2]) {
    asm volatile(
        "mma.sync.aligned.m16n8k8.row.col.f32.tf32.tf32.f32 "
        "{%0,%1,%2,%3}, {%4,%5,%6,%7}, {%8,%9}, {%0,%1,%2,%3};\n"
        : "+f"(c[0]), "+f"(c[1]), "+f"(c[2]), "+f"(c[3])
        : "r"(a[0]), "r"(a[1]), "r"(a[2]), "r"(a[3]), "r"(b[0]), "r"(b[1]));
}

__device__ __forceinline__ void cpa16(uint32_t saddr, const void* g) {
    asm volatile("cp.async.cg.shared.global [%0], [%1], 16;" :: "r"(saddr), "l"(g));
}
#define CP_COMMIT() asm volatile("cp.async.commit_group;")
#define CP_WAIT(N)  asm volatile("cp.async.wait_group %0;" :: "n"(N))

__device__ __forceinline__ float silu(float x) {
    return x * (1.0f / (1.0f + __expf(-x)));
}

// ---------------- kernel 0 ----------------
__global__ void k_zero() {
    if (threadIdx.x < E_NUM) g_cnt[threadIdx.x] = 0;
}

// ---------------- pre-round to tf32 ----------------
__global__ void k_cvt(const float* __restrict__ src, float* __restrict__ dst) {
    size_t i = ((size_t)blockIdx.x * blockDim.x + threadIdx.x) * 4;
    float4 v = *(const float4*)(src + i);
    v.x = __uint_as_float(f2tf(v.x));
    v.y = __uint_as_float(f2tf(v.y));
    v.z = __uint_as_float(f2tf(v.z));
    v.w = __uint_as_float(f2tf(v.w));
    *(float4*)(dst + i) = v;
}

// ---------------- kernel 1: router (smem-tiled gw) ----------------
__global__ __launch_bounds__(256) void k_router(const float* __restrict__ x,
                                                const float* __restrict__ gw,
                                                float* __restrict__ out, int write_ids) {
    __shared__ float s_gw[64 * E_NUM];  // 8 KB
    int tid  = threadIdx.x;
    int wid  = tid >> 5, lane = tid & 31;
    int tok  = blockIdx.x * 8 + wid;

    const float* xr = x + (size_t)tok * H_DIM;
    float acc = 0.0f;
    for (int h0 = 0; h0 < H_DIM; h0 += 64) {
#pragma unroll
        for (int i = 0; i < 8; i++) s_gw[tid + i * 256] = gw[h0 * E_NUM + tid + i * 256];
        __syncthreads();
#pragma unroll 16
        for (int hh = 0; hh < 64; hh++) acc += xr[h0 + hh] * s_gw[hh * E_NUM + lane];
        __syncthreads();
    }

    float m = acc;
#pragma unroll
    for (int o = 16; o; o >>= 1) m = fmaxf(m, __shfl_xor_sync(0xffffffffu, m, o));
    float p = expf(acc - m);
    float s = p;
#pragma unroll
    for (int o = 16; o; o >>= 1) s += __shfl_xor_sync(0xffffffffu, s, o);
    float score = p / s;

    float val = score;
    int   ids[TOPK];
    float ws[TOPK];
    float wsum = 0.0f;
#pragma unroll
    for (int j = 0; j < TOPK; j++) {
        float bv = val;
        int   bi = lane;
#pragma unroll
        for (int o = 16; o; o >>= 1) {
            float ov = __shfl_xor_sync(0xffffffffu, bv, o);
            int   oi = __shfl_xor_sync(0xffffffffu, bi, o);
            if (ov > bv || (ov == bv && oi < bi)) { bv = ov; bi = oi; }
        }
        ids[j] = bi; ws[j] = bv; wsum += bv;
        if (lane == bi) val = -1.0f;
    }

    if (lane == 0) {
        float inv = 1.0f / wsum;
#pragma unroll
        for (int j = 0; j < TOPK; j++) {
            g_topk_ids[tok * TOPK + j] = ids[j];
            g_topk_w[tok * TOPK + j]   = ws[j] * inv;
            atomicAdd(&g_cnt[ids[j]], 1);
            if (write_ids)
                out[(size_t)T_TOK * H_DIM + tok * TOPK + j] = (float)ids[j];
        }
    }
}

// ---------------- kernel 2/3 ----------------
__global__ void k_scan() {
    if (threadIdx.x == 0) {
        int acc = 0;
        for (int e = 0; e < E_NUM; e++) { g_off[e] = acc; g_pos[e] = acc; acc += g_cnt[e]; }
        g_off[E_NUM] = acc;
    }
}

__global__ void k_scatter() {
    int pp = blockIdx.x * blockDim.x + threadIdx.x;
    if (pp >= P_NUM) return;
    int e = g_topk_ids[pp];
    int slot = atomicAdd(&g_pos[e], 1);
    g_slot_token[slot] = pp >> 3;
    g_slot_w[slot]     = g_topk_w[pp];
    g_pair2slot[pp]    = slot;
}

// ================= kernel 4: fused gate+up GEMM + SwiGLU =================
// Block 128M x 64N, BK=32, 2-stage cp.async, ONE sync/K-tile, 8 warps, 2 CTAs/SM.
#define A_STRIDE 36
#define A_TILE   (128 * A_STRIDE)   // 4608 floats / stage
#define BG_STRIDE 72
#define BG_TILE  (32 * BG_STRIDE)   // 2304 floats / stage

__global__ __launch_bounds__(256, 2) void k_gemmA(const float* __restrict__ x,
                                                  const float* __restrict__ wgate,
                                                  const float* __restrict__ wup) {
    int e   = blockIdx.z;
    int cnt = g_cnt[e];
    int m0  = blockIdx.y * 128;
    if (m0 >= cnt) return;
    int n0   = blockIdx.x * 64;
    int base = g_off[e];
    int tid  = threadIdx.x;

    extern __shared__ float smem[];
    float* AsB = smem;                       // 2 stages
    float* BgB = smem + 2 * A_TILE;
    float* BuB = smem + 2 * A_TILE + 2 * BG_TILE;
    uint32_t sbase = (uint32_t)__cvta_generic_to_shared(smem);

    __shared__ int s_tok[128];
    if (tid < 128) {
        int m = m0 + tid;
        s_tok[tid] = g_slot_token[base + ((m < cnt) ? m : 0)];
    }
    __syncthreads();

    const float* wgb = wgate + (size_t)e * H_DIM * I_DIM + n0;
    const float* wub = wup   + (size_t)e * H_DIM * I_DIM + n0;

    int ac = tid & 7,  ar = tid >> 3;
    int bc = tid & 15, br = tid >> 4;

    const int NT = H_DIM / 32;  // 64

    auto load_stage = [&](int t, int s) {
        int k0 = t * 32;
        uint32_t aoff = sbase + (uint32_t)(s * A_TILE) * 4u;
        uint32_t goff = sbase + (uint32_t)(2 * A_TILE + s * BG_TILE) * 4u;
        uint32_t uoff = sbase + (uint32_t)(2 * A_TILE + 2 * BG_TILE + s * BG_TILE) * 4u;
#pragma unroll
        for (int i = 0; i < 4; i++) {
            int r = ar + i * 32;
            cpa16(aoff + (uint32_t)(r * A_STRIDE + ac * 4) * 4u,
                  x + (size_t)s_tok[r] * H_DIM + k0 + ac * 4);
        }
#pragma unroll
        for (int i = 0; i < 2; i++) {
            int kr = br + i * 16;
            uint32_t so = (uint32_t)(kr * BG_STRIDE + bc * 4) * 4u;
            cpa16(goff + so, wgb + (size_t)(k0 + kr) * I_DIM + bc * 4);
            cpa16(uoff + so, wub + (size_t)(k0 + kr) * I_DIM + bc * 4);
        }
        CP_COMMIT();
    };

    int wid = tid >> 5, lane = tid & 31;
    int wm = (wid & 3) * 32, wn = (wid >> 2) * 32;
    int gid = lane >> 2, tig = lane & 3;

    float cg[2][4][4], cu[2][4][4];
#pragma unroll
    for (int i = 0; i < 2; i++)
#pragma unroll
        for (int j = 0; j < 4; j++)
#pragma unroll
            for (int q = 0; q < 4; q++) { cg[i][j][q] = 0.0f; cu[i][j][q] = 0.0f; }

    load_stage(0, 0);

    for (int t = 0; t < NT; t++) {
        CP_WAIT(0);          // load(t) complete
        __syncthreads();     // all warps done reading buf[(t+1)&1] from iter t-1
        if (t + 1 < NT) load_stage(t + 1, (t + 1) & 1);   // overlaps compute(t)

        const float* As = AsB + (t & 1) * A_TILE;
        const float* Bg = BgB + (t & 1) * BG_TILE;
        const float* Bu = BuB + (t & 1) * BG_TILE;

#pragma unroll
        for (int kf = 0; kf < 32; kf += 8) {
            uint32_t a[2][4];
#pragma unroll
            for (int mf = 0; mf < 2; mf++) {
                int rb = wm + mf * 16;
                a[mf][0] = __float_as_uint(As[(rb + gid) * A_STRIDE + kf + tig]);
                a[mf][1] = __float_as_uint(As[(rb + gid + 8) * A_STRIDE + kf + tig]);
                a[mf][2] = __float_as_uint(As[(rb + gid) * A_STRIDE + kf + tig + 4]);
                a[mf][3] = __float_as_uint(As[(rb + gid + 8) * A_STRIDE + kf + tig + 4]);
            }
            uint32_t bg[4][2], bu[4][2];
#pragma unroll
            for (int nf = 0; nf < 4; nf++) {
                int cb = wn + nf * 8 + gid;
                bg[nf][0] = __float_as_uint(Bg[(kf + tig) * BG_STRIDE + cb]);
                bg[nf][1] = __float_as_uint(Bg[(kf + tig + 4) * BG_STRIDE + cb]);
                bu[nf][0] = __float_as_uint(Bu[(kf + tig) * BG_STRIDE + cb]);
                bu[nf][1] = __float_as_uint(Bu[(kf + tig + 4) * BG_STRIDE + cb]);
            }
#pragma unroll
            for (int mf = 0; mf < 2; mf++)
#pragma unroll
                for (int nf = 0; nf < 4; nf++) {
                    mma8(cg[mf][nf], a[mf], bg[nf]);
                    mma8(cu[mf][nf], a[mf], bu[nf]);
                }
        }
    }

    // epilogue: h = silu(g)*u, tf32-rounded
#pragma unroll
    for (int mf = 0; mf < 2; mf++)
#pragma unroll
        for (int nf = 0; nf < 4; nf++) {
            int col = n0 + wn + nf * 8 + 2 * tig;
            int r1 = wm + mf * 16 + gid;
            int r2 = r1 + 8;
            int m1 = m0 + r1, m2 = m0 + r2;
            if (m1 < cnt) {
                float2 v = make_float2(
                    __uint_as_float(f2tf(silu(cg[mf][nf][0]) * cu[mf][nf][0])),
                    __uint_as_float(f2tf(silu(cg[mf][nf][1]) * cu[mf][nf][1])));
                *(float2*)&g_hbuf[(size_t)(base + m1) * I_DIM + col] = v;
            }
            if (m2 < cnt) {
                float2 v = make_float2(
                    __uint_as_float(f2tf(silu(cg[mf][nf][2]) * cu[mf][nf][2])),
                    __uint_as_float(f2tf(silu(cg[mf][nf][3]) * cu[mf][nf][3])));
                *(float2*)&g_hbuf[(size_t)(base + m2) * I_DIM + col] = v;
            }
        }
}

// ================= kernel 5: down GEMM (weighted) =================
// Block 128M x 128N, BK=32, 2-stage cp.async, ONE sync/K-tile, 8 warps, 2 CTAs/SM.
#define BD_STRIDE 136
#define BD_TILE   (32 * BD_STRIDE)   // 4352 floats / stage

__global__ __launch_bounds__(256, 2) void k_gemmB(const float* __restrict__ wdown) {
    int e   = blockIdx.z;
    int cnt = g_cnt[e];
    int m0  = blockIdx.y * 128;
    if (m0 >= cnt) return;
    int n0   = blockIdx.x * 128;
    int base = g_off[e];
    int tid  = threadIdx.x;

    extern __shared__ float smem[];
    float* AsB = smem;
    float* BsB = smem + 2 * A_TILE;
    uint32_t sbase = (uint32_t)__cvta_generic_to_shared(smem);

    const float* wb = wdown + (size_t)e * I_DIM * H_DIM + n0;

    int ac = tid & 7,  ar = tid >> 3;
    int bc = tid & 31, br = tid >> 5;

    const int NT = I_DIM / 32;  // 32

    auto load_stage = [&](int t, int s) {
        int k0 = t * 32;
        uint32_t aoff = sbase + (uint32_t)(s * A_TILE) * 4u;
        uint32_t boff = sbase + (uint32_t)(2 * A_TILE + s * BD_TILE) * 4u;
#pragma unroll
        for (int i = 0; i < 4; i++) {
            int r = ar + i * 32;
            int m = m0 + r;
            int slot = base + ((m < cnt) ? m : (cnt - 1));
            cpa16(aoff + (uint32_t)(r * A_STRIDE + ac * 4) * 4u,
                  &g_hbuf[(size_t)slot * I_DIM + k0 + ac * 4]);
        }
#pragma unroll
        for (int i = 0; i < 4; i++) {
            int kr = br + i * 8;
            cpa16(boff + (uint32_t)(kr * BD_STRIDE + bc * 4) * 4u,
                  wb + (size_t)(k0 + kr) * H_DIM + bc * 4);
        }
        CP_COMMIT();
    };

    int wid = tid >> 5, lane = tid & 31;
    int wm = (wid & 3) * 32, wn = (wid >> 2) * 64;
    int gid = lane >> 2, tig = lane & 3;

    float cc[2][8][4];
#pragma unroll
    for (int i = 0; i < 2; i++)
#pragma unroll
        for (int j = 0; j < 8; j++)
#pragma unroll
            for (int q = 0; q < 4; q++) cc[i][j][q] = 0.0f;

    load_stage(0, 0);

    for (int t = 0; t < NT; t++) {
        CP_WAIT(0);
        __syncthreads();
        if (t + 1 < NT) load_stage(t + 1, (t + 1) & 1);

        const float* As = AsB + (t & 1) * A_TILE;
        const float* Bs = BsB + (t & 1) * BD_TILE;

#pragma unroll
        for (int kf = 0; kf < 32; kf += 8) {
            uint32_t a[2][4];
#pragma unroll
            for (int mf = 0; mf < 2; mf++) {
                int rb = wm + mf * 16;
                a[mf][0] = __float_as_uint(As[(rb + gid) * A_STRIDE + kf + tig]);
                a[mf][1] = __float_as_uint(As[(rb + gid + 8) * A_STRIDE + kf + tig]);
                a[mf][2] = __float_as_uint(As[(rb + gid) * A_STRIDE + kf + tig + 4]);
                a[mf][3] = __float_as_uint(As[(rb + gid + 8) * A_STRIDE + kf + tig + 4]);
            }
            uint32_t b[8][2];
#pragma unroll
            for (int nf = 0; nf < 8; nf++) {
                int cb = wn + nf * 8 + gid;
                b[nf][0] = __float_as_uint(Bs[(kf + tig) * BD_STRIDE + cb]);
                b[nf][1] = __float_as_uint(Bs[(kf + tig + 4) * BD_STRIDE + cb]);
            }
#pragma unroll
            for (int mf = 0; mf < 2; mf++)
#pragma unroll
                for (int nf = 0; nf < 8; nf++) mma8(cc[mf][nf], a[mf], b[nf]);
        }
    }

#pragma unroll
    for (int mf = 0; mf < 2; mf++) {
        int r1 = wm + mf * 16 + gid;
        int r2 = r1 + 8;
        int m1 = m0 + r1, m2 = m0 + r2;
        float w1 = (m1 < cnt) ? g_slot_w[base + m1] : 0.0f;
        float w2 = (m2 < cnt) ? g_slot_w[base + m2] : 0.0f;
#pragma unroll
        for (int nf = 0; nf < 8; nf++) {
            int col = n0 + wn + nf * 8 + 2 * tig;
            if (m1 < cnt) {
                float2 v = make_float2(cc[mf][nf][0] * w1, cc[mf][nf][1] * w1);
                *(float2*)&g_dbuf[(size_t)(base + m1) * H_DIM + col] = v;
            }
            if (m2 < cnt) {
                float2 v = make_float2(cc[mf][nf][2] * w2, cc[mf][nf][3] * w2);
                *(float2*)&g_dbuf[(size_t)(base + m2) * H_DIM + col] = v;
            }
        }
    }
}

// ---------------- kernel 6: combine ----------------
__global__ void k_reduce(float* __restrict__ out) {
    int idx4 = blockIdx.x * blockDim.x + threadIdx.x;
    int t  = idx4 >> 9;
    int h4 = idx4 & 511;
    const int* ps = &g_pair2slot[t * TOPK];
    float4 s = make_float4(0.f, 0.f, 0.f, 0.f);
#pragma unroll
    for (int k = 0; k < TOPK; k++) {
        const float4 v = *(const float4*)&g_dbuf[(size_t)ps[k] * H_DIM + h4 * 4];
        s.x += v.x; s.y += v.y; s.z += v.z; s.w += v.w;
    }
    *(float4*)&out[(size_t)idx4 * 4] = s;
}

// ---------------- launch ----------------
extern "C" void kernel_launch(void* const* d_in, const int* in_sizes, int n_in,
                              void* d_out, int out_size) {
    const float* x  = (const float*)d_in[0];
    const float* gw = (const float*)d_in[1];
    const float* wg = (const float*)d_in[2];
    const float* wu = (const float*)d_in[3];
    const float* wd = (const float*)d_in[4];
    float* out = (float*)d_out;

    int write_ids = (out_size >= T_TOK * H_DIM + P_NUM) ? 1 : 0;

    const int smemA = (2 * A_TILE + 4 * BG_TILE) * 4;   // 73728 B  -> 2 CTAs/SM
    const int smemB = (2 * A_TILE + 2 * BD_TILE) * 4;   // 71680 B  -> 2 CTAs/SM
    cudaFuncSetAttribute(k_gemmA, cudaFuncAttributeMaxDynamicSharedMemorySize, smemA);
    cudaFuncSetAttribute(k_gemmB, cudaFuncAttributeMaxDynamicSharedMemorySize, smemB);

    k_zero<<<1, 32>>>();
    k_router<<<T_TOK / 8, 256>>>(x, gw, out, write_ids);
    k_scan<<<1, 32>>>();
    k_scatter<<<P_NUM / 256, 256>>>();

    float* wg_t; float* wu_t; float* wd_t; float* x_t;
    cudaGetSymbolAddress((void**)&wg_t, g_wg_t);
    cudaGetSymbolAddress((void**)&wu_t, g_wu_t);
    cudaGetSymbolAddress((void**)&wd_t, g_wd_t);
    cudaGetSymbolAddress((void**)&x_t,  g_x_t);
    k_cvt<<<(int)(W_ELEMS / 4 / 256), 256>>>(wg, wg_t);
    k_cvt<<<(int)(W_ELEMS / 4 / 256), 256>>>(wu, wu_t);
    k_cvt<<<(int)(W_ELEMS / 4 / 256), 256>>>(wd, wd_t);
    k_cvt<<<(T_TOK * H_DIM / 4) / 256, 256>>>(x, x_t);

    dim3 ga(I_DIM / 64, T_TOK / 128, E_NUM);   // (16, 32, 32)
    k_gemmA<<<ga, 256, smemA>>>(x_t, wg_t, wu_t);

    dim3 gb(H_DIM / 128, T_TOK / 128, E_NUM);  // (16, 32, 32)
    k_gemmB<<<gb, 256, smemB>>>(wd_t);

    k_reduce<<<(T_TOK * H_DIM / 4) / 256, 256>>>(out);
}

// round 9
// speedup vs baseline: 1.2362x; 1.0446x over previous
#include <cuda_runtime.h>
#include <cstdint>
#include <math.h>

// Problem constants
#define T_TOK 4096
#define H_DIM 2048
#define E_NUM 32
#define I_DIM 1024
#define TOPK  8
#define P_NUM (T_TOK * TOPK)
#define W_ELEMS ((size_t)E_NUM * H_DIM * I_DIM)

// ---------------- scratch ----------------
__device__ int   g_topk_ids[P_NUM];
__device__ float g_topk_w[P_NUM];
__device__ int   g_cnt[E_NUM];
__device__ int   g_pos[E_NUM];
__device__ int   g_off[E_NUM + 1];
__device__ int   g_slot_token[P_NUM];
__device__ float g_slot_w[P_NUM];
__device__ int   g_pair2slot[P_NUM];
__device__ float g_hbuf[(size_t)P_NUM * I_DIM];   // tf32-rounded activations
__device__ float g_dbuf[(size_t)P_NUM * H_DIM];
// tf32-pre-rounded operands; weights stored TRANSPOSED (n-major) for ldmatrix
__device__ float g_x_t[(size_t)T_TOK * H_DIM];
__device__ float g_wg_t[W_ELEMS];   // [E][I][H]
__device__ float g_wu_t[W_ELEMS];   // [E][I][H]
__device__ float g_wd_t[W_ELEMS];   // [E][H][I]

// ---------------- helpers ----------------
__device__ __forceinline__ uint32_t f2tf(float f) {
    uint32_t u;
    asm("cvt.rna.tf32.f32 %0, %1;" : "=r"(u) : "f"(f));
    return u;
}

__device__ __forceinline__ void mma8(float c[4], const uint32_t a[4], const uint32_t b[2]) {
    asm volatile(
        "mma.sync.aligned.m16n8k8.row.col.f32.tf32.tf32.f32 "
        "{%0,%1,%2,%3}, {%4,%5,%6,%7}, {%8,%9}, {%0,%1,%2,%3};\n"
        : "+f"(c[0]), "+f"(c[1]), "+f"(c[2]), "+f"(c[3])
        : "r"(a[0]), "r"(a[1]), "r"(a[2]), "r"(a[3]), "r"(b[0]), "r"(b[1]));
}

__device__ __forceinline__ void ldsm4(uint32_t& r0, uint32_t& r1, uint32_t& r2,
                                      uint32_t& r3, uint32_t addr) {
    asm volatile("ldmatrix.sync.aligned.m8n8.x4.shared.b16 {%0,%1,%2,%3}, [%4];"
                 : "=r"(r0), "=r"(r1), "=r"(r2), "=r"(r3) : "r"(addr));
}

__device__ __forceinline__ void cpa16(uint32_t saddr, const void* g) {
    asm volatile("cp.async.cg.shared.global [%0], [%1], 16;" :: "r"(saddr), "l"(g));
}
#define CP_COMMIT() asm volatile("cp.async.commit_group;")
#define CP_WAIT(N)  asm volatile("cp.async.wait_group %0;" :: "n"(N))

__device__ __forceinline__ float silu(float x) {
    return x * (1.0f / (1.0f + __expf(-x)));
}

// ---------------- kernel 0 ----------------
__global__ void k_zero() {
    if (threadIdx.x < E_NUM) g_cnt[threadIdx.x] = 0;
}

// ---------------- straight cvt (x) ----------------
__global__ void k_cvt(const float* __restrict__ src, float* __restrict__ dst) {
    size_t i = ((size_t)blockIdx.x * blockDim.x + threadIdx.x) * 4;
    float4 v = *(const float4*)(src + i);
    v.x = __uint_as_float(f2tf(v.x));
    v.y = __uint_as_float(f2tf(v.y));
    v.z = __uint_as_float(f2tf(v.z));
    v.w = __uint_as_float(f2tf(v.w));
    *(float4*)(dst + i) = v;
}

// ---------------- transposing cvt: src [E][R][C] -> dst [E][C][R], tf32-rounded ----
__global__ __launch_bounds__(256) void k_cvt_t(const float* __restrict__ src,
                                               float* __restrict__ dst, int R, int C) {
    __shared__ float tile[32][33];
    int e  = blockIdx.z;
    int c0 = blockIdx.x * 32, r0 = blockIdx.y * 32;
    const float* s = src + (size_t)e * R * C;
    float*       d = dst + (size_t)e * R * C;
    int tx = threadIdx.x & 31, ty = threadIdx.x >> 5;   // 32 x 8
#pragma unroll
    for (int i = 0; i < 32; i += 8) {
        float v = s[(size_t)(r0 + ty + i) * C + c0 + tx];
        tile[ty + i][tx] = __uint_as_float(f2tf(v));
    }
    __syncthreads();
#pragma unroll
    for (int i = 0; i < 32; i += 8) {
        d[(size_t)(c0 + ty + i) * R + r0 + tx] = tile[tx][ty + i];
    }
}

// ---------------- kernel 1: router (smem-tiled gw) ----------------
__global__ __launch_bounds__(256) void k_router(const float* __restrict__ x,
                                                const float* __restrict__ gw,
                                                float* __restrict__ out, int write_ids) {
    __shared__ float s_gw[64 * E_NUM];
    int tid  = threadIdx.x;
    int wid  = tid >> 5, lane = tid & 31;
    int tok  = blockIdx.x * 8 + wid;

    const float* xr = x + (size_t)tok * H_DIM;
    float acc = 0.0f;
    for (int h0 = 0; h0 < H_DIM; h0 += 64) {
#pragma unroll
        for (int i = 0; i < 8; i++) s_gw[tid + i * 256] = gw[h0 * E_NUM + tid + i * 256];
        __syncthreads();
#pragma unroll 16
        for (int hh = 0; hh < 64; hh++) acc += xr[h0 + hh] * s_gw[hh * E_NUM + lane];
        __syncthreads();
    }

    float m = acc;
#pragma unroll
    for (int o = 16; o; o >>= 1) m = fmaxf(m, __shfl_xor_sync(0xffffffffu, m, o));
    float p = expf(acc - m);
    float s = p;
#pragma unroll
    for (int o = 16; o; o >>= 1) s += __shfl_xor_sync(0xffffffffu, s, o);
    float score = p / s;

    float val = score;
    int   ids[TOPK];
    float ws[TOPK];
    float wsum = 0.0f;
#pragma unroll
    for (int j = 0; j < TOPK; j++) {
        float bv = val;
        int   bi = lane;
#pragma unroll
        for (int o = 16; o; o >>= 1) {
            float ov = __shfl_xor_sync(0xffffffffu, bv, o);
            int   oi = __shfl_xor_sync(0xffffffffu, bi, o);
            if (ov > bv || (ov == bv && oi < bi)) { bv = ov; bi = oi; }
        }
        ids[j] = bi; ws[j] = bv; wsum += bv;
        if (lane == bi) val = -1.0f;
    }

    if (lane == 0) {
        float inv = 1.0f / wsum;
#pragma unroll
        for (int j = 0; j < TOPK; j++) {
            g_topk_ids[tok * TOPK + j] = ids[j];
            g_topk_w[tok * TOPK + j]   = ws[j] * inv;
            atomicAdd(&g_cnt[ids[j]], 1);
            if (write_ids)
                out[(size_t)T_TOK * H_DIM + tok * TOPK + j] = (float)ids[j];
        }
    }
}

// ---------------- kernel 2/3 ----------------
__global__ void k_scan() {
    if (threadIdx.x == 0) {
        int acc = 0;
        for (int e = 0; e < E_NUM; e++) { g_off[e] = acc; g_pos[e] = acc; acc += g_cnt[e]; }
        g_off[E_NUM] = acc;
    }
}

__global__ void k_scatter() {
    int pp = blockIdx.x * blockDim.x + threadIdx.x;
    if (pp >= P_NUM) return;
    int e = g_topk_ids[pp];
    int slot = atomicAdd(&g_pos[e], 1);
    g_slot_token[slot] = pp >> 3;
    g_slot_w[slot]     = g_topk_w[pp];
    g_pair2slot[pp]    = slot;
}

// ================= GEMM tiling constants =================
#define A_STRIDE 36
#define A_TILE   (128 * A_STRIDE)   // 4608 floats / stage
#define B_STRIDE 36                 // n-major B rows: 32 k-floats + pad
#define BA_TILE  (64  * B_STRIDE)   // gemmA: 64 n-rows  = 2304 floats / stage
#define BB_TILE  (128 * B_STRIDE)   // gemmB: 128 n-rows = 4608 floats / stage

// ================= kernel 4: fused gate+up GEMM + SwiGLU =================
// Block 128M x 64N, BK=32, 2-stage cp.async, one sync/K-tile, 8 warps, 2 CTAs/SM.
// A and B fragments loaded via ldmatrix.x4 (tf32-as-b16 trick); B is n-major.
__global__ __launch_bounds__(256, 2) void k_gemmA(const float* __restrict__ x,
                                                  const float* __restrict__ wgate,
                                                  const float* __restrict__ wup) {
    int e   = blockIdx.z;
    int cnt = g_cnt[e];
    int m0  = blockIdx.y * 128;
    if (m0 >= cnt) return;
    int n0   = blockIdx.x * 64;
    int base = g_off[e];
    int tid  = threadIdx.x;

    extern __shared__ float smem[];
    uint32_t sbase = (uint32_t)__cvta_generic_to_shared(smem);

    __shared__ int s_tok[128];
    if (tid < 128) {
        int m = m0 + tid;
        s_tok[tid] = g_slot_token[base + ((m < cnt) ? m : 0)];
    }
    __syncthreads();

    // wgate/wup are n-major: [E][I][H]
    const float* wgb = wgate + ((size_t)e * I_DIM + n0) * H_DIM;
    const float* wub = wup   + ((size_t)e * I_DIM + n0) * H_DIM;

    int ac = tid & 7, ar = tid >> 3;   // 8 chunks/row, 32 rows/pass

    const int NT = H_DIM / 32;  // 64

    auto load_stage = [&](int t, int s) {
        int k0 = t * 32;
        uint32_t aoff = sbase + (uint32_t)(s * A_TILE) * 4u;
        uint32_t goff = sbase + (uint32_t)(2 * A_TILE + s * BA_TILE) * 4u;
        uint32_t uoff = sbase + (uint32_t)(2 * A_TILE + 2 * BA_TILE + s * BA_TILE) * 4u;
#pragma unroll
        for (int i = 0; i < 4; i++) {
            int r = ar + i * 32;
            cpa16(aoff + (uint32_t)(r * A_STRIDE + ac * 4) * 4u,
                  x + (size_t)s_tok[r] * H_DIM + k0 + ac * 4);
        }
#pragma unroll
        for (int i = 0; i < 2; i++) {
            int r = ar + i * 32;   // n-row 0..63
            uint32_t so = (uint32_t)(r * B_STRIDE + ac * 4) * 4u;
            cpa16(goff + so, wgb + (size_t)r * H_DIM + k0 + ac * 4);
            cpa16(uoff + so, wub + (size_t)r * H_DIM + k0 + ac * 4);
        }
        CP_COMMIT();
    };

    int wid = tid >> 5, lane = tid & 31;
    int wm = (wid & 3) * 32, wn = (wid >> 2) * 32;
    int gid = lane >> 2, tig = lane & 3;

    // per-lane ldmatrix row/col offsets
    int a_row = lane & 15, a_col = (lane >> 4) << 2;             // A tiles
    int b_rowo = ((lane >> 4) << 3) + (lane & 7);                // B tiles
    int b_colo = ((lane >> 3) & 1) << 2;

    float cg[2][4][4], cu[2][4][4];
#pragma unroll
    for (int i = 0; i < 2; i++)
#pragma unroll
        for (int j = 0; j < 4; j++)
#pragma unroll
            for (int q = 0; q < 4; q++) { cg[i][j][q] = 0.0f; cu[i][j][q] = 0.0f; }

    load_stage(0, 0);

    for (int t = 0; t < NT; t++) {
        CP_WAIT(0);
        __syncthreads();
        if (t + 1 < NT) load_stage(t + 1, (t + 1) & 1);

        uint32_t sA = sbase + (uint32_t)((t & 1) * A_TILE) * 4u;
        uint32_t sG = sbase + (uint32_t)(2 * A_TILE + (t & 1) * BA_TILE) * 4u;
        uint32_t sU = sbase + (uint32_t)(2 * A_TILE + 2 * BA_TILE + (t & 1) * BA_TILE) * 4u;

#pragma unroll
        for (int kf = 0; kf < 32; kf += 8) {
            uint32_t a[2][4], bg[4][2], bu[4][2];
#pragma unroll
            for (int mf = 0; mf < 2; mf++) {
                uint32_t addr = sA + (uint32_t)((wm + mf * 16 + a_row) * A_STRIDE
                                                + kf + a_col) * 4u;
                ldsm4(a[mf][0], a[mf][1], a[mf][2], a[mf][3], addr);
            }
#pragma unroll
            for (int p = 0; p < 2; p++) {
                uint32_t so = (uint32_t)((wn + p * 16 + b_rowo) * B_STRIDE
                                         + kf + b_colo) * 4u;
                ldsm4(bg[2*p][0], bg[2*p][1], bg[2*p+1][0], bg[2*p+1][1], sG + so);
                ldsm4(bu[2*p][0], bu[2*p][1], bu[2*p+1][0], bu[2*p+1][1], sU + so);
            }
#pragma unroll
            for (int mf = 0; mf < 2; mf++)
#pragma unroll
                for (int nf = 0; nf < 4; nf++) {
                    mma8(cg[mf][nf], a[mf], bg[nf]);
                    mma8(cu[mf][nf], a[mf], bu[nf]);
                }
        }
    }

    // epilogue: h = silu(g)*u, tf32-rounded
#pragma unroll
    for (int mf = 0; mf < 2; mf++)
#pragma unroll
        for (int nf = 0; nf < 4; nf++) {
            int col = n0 + wn + nf * 8 + 2 * tig;
            int r1 = wm + mf * 16 + gid;
            int r2 = r1 + 8;
            int m1 = m0 + r1, m2 = m0 + r2;
            if (m1 < cnt) {
                float2 v = make_float2(
                    __uint_as_float(f2tf(silu(cg[mf][nf][0]) * cu[mf][nf][0])),
                    __uint_as_float(f2tf(silu(cg[mf][nf][1]) * cu[mf][nf][1])));
                *(float2*)&g_hbuf[(size_t)(base + m1) * I_DIM + col] = v;
            }
            if (m2 < cnt) {
                float2 v = make_float2(
                    __uint_as_float(f2tf(silu(cg[mf][nf][2]) * cu[mf][nf][2])),
                    __uint_as_float(f2tf(silu(cg[mf][nf][3]) * cu[mf][nf][3])));
                *(float2*)&g_hbuf[(size_t)(base + m2) * I_DIM + col] = v;
            }
        }
}

// ================= kernel 5: down GEMM (weighted) =================
// Block 128M x 128N, BK=32, 2-stage cp.async, one sync/K-tile, 8 warps, 2 CTAs/SM.
__global__ __launch_bounds__(256, 2) void k_gemmB(const float* __restrict__ wdown) {
    int e   = blockIdx.z;
    int cnt = g_cnt[e];
    int m0  = blockIdx.y * 128;
    if (m0 >= cnt) return;
    int n0   = blockIdx.x * 128;
    int base = g_off[e];
    int tid  = threadIdx.x;

    extern __shared__ float smem[];
    uint32_t sbase = (uint32_t)__cvta_generic_to_shared(smem);

    // wdown is n-major: [E][H][I]
    const float* wb = wdown + ((size_t)e * H_DIM + n0) * I_DIM;

    int ac = tid & 7, ar = tid >> 3;

    const int NT = I_DIM / 32;  // 32

    auto load_stage = [&](int t, int s) {
        int k0 = t * 32;
        uint32_t aoff = sbase + (uint32_t)(s * A_TILE) * 4u;
        uint32_t boff = sbase + (uint32_t)(2 * A_TILE + s * BB_TILE) * 4u;
#pragma unroll
        for (int i = 0; i < 4; i++) {
            int r = ar + i * 32;
            int m = m0 + r;
            int slot = base + ((m < cnt) ? m : (cnt - 1));
            cpa16(aoff + (uint32_t)(r * A_STRIDE + ac * 4) * 4u,
                  &g_hbuf[(size_t)slot * I_DIM + k0 + ac * 4]);
        }
#pragma unroll
        for (int i = 0; i < 4; i++) {
            int r = ar + i * 32;   // n-row 0..127
            cpa16(boff + (uint32_t)(r * B_STRIDE + ac * 4) * 4u,
                  wb + (size_t)r * I_DIM + k0 + ac * 4);
        }
        CP_COMMIT();
    };

    int wid = tid >> 5, lane = tid & 31;
    int wm = (wid & 3) * 32, wn = (wid >> 2) * 64;
    int gid = lane >> 2, tig = lane & 3;

    int a_row = lane & 15, a_col = (lane >> 4) << 2;
    int b_rowo = ((lane >> 4) << 3) + (lane & 7);
    int b_colo = ((lane >> 3) & 1) << 2;

    float cc[2][8][4];
#pragma unroll
    for (int i = 0; i < 2; i++)
#pragma unroll
        for (int j = 0; j < 8; j++)
#pragma unroll
            for (int q = 0; q < 4; q++) cc[i][j][q] = 0.0f;

    load_stage(0, 0);

    for (int t = 0; t < NT; t++) {
        CP_WAIT(0);
        __syncthreads();
        if (t + 1 < NT) load_stage(t + 1, (t + 1) & 1);

        uint32_t sA = sbase + (uint32_t)((t & 1) * A_TILE) * 4u;
        uint32_t sB = sbase + (uint32_t)(2 * A_TILE + (t & 1) * BB_TILE) * 4u;

#pragma unroll
        for (int kf = 0; kf < 32; kf += 8) {
            uint32_t a[2][4], b[8][2];
#pragma unroll
            for (int mf = 0; mf < 2; mf++) {
                uint32_t addr = sA + (uint32_t)((wm + mf * 16 + a_row) * A_STRIDE
                                                + kf + a_col) * 4u;
                ldsm4(a[mf][0], a[mf][1], a[mf][2], a[mf][3], addr);
            }
#pragma unroll
            for (int p = 0; p < 4; p++) {
                uint32_t so = (uint32_t)((wn + p * 16 + b_rowo) * B_STRIDE
                                         + kf + b_colo) * 4u;
                ldsm4(b[2*p][0], b[2*p][1], b[2*p+1][0], b[2*p+1][1], sB + so);
            }
#pragma unroll
            for (int mf = 0; mf < 2; mf++)
#pragma unroll
                for (int nf = 0; nf < 8; nf++) mma8(cc[mf][nf], a[mf], b[nf]);
        }
    }

#pragma unroll
    for (int mf = 0; mf < 2; mf++) {
        int r1 = wm + mf * 16 + gid;
        int r2 = r1 + 8;
        int m1 = m0 + r1, m2 = m0 + r2;
        float w1 = (m1 < cnt) ? g_slot_w[base + m1] : 0.0f;
        float w2 = (m2 < cnt) ? g_slot_w[base + m2] : 0.0f;
#pragma unroll
        for (int nf = 0; nf < 8; nf++) {
            int col = n0 + wn + nf * 8 + 2 * tig;
            if (m1 < cnt) {
                float2 v = make_float2(cc[mf][nf][0] * w1, cc[mf][nf][1] * w1);
                *(float2*)&g_dbuf[(size_t)(base + m1) * H_DIM + col] = v;
            }
            if (m2 < cnt) {
                float2 v = make_float2(cc[mf][nf][2] * w2, cc[mf][nf][3] * w2);
                *(float2*)&g_dbuf[(size_t)(base + m2) * H_DIM + col] = v;
            }
        }
    }
}

// ---------------- kernel 6: combine ----------------
__global__ void k_reduce(float* __restrict__ out) {
    int idx4 = blockIdx.x * blockDim.x + threadIdx.x;
    int t  = idx4 >> 9;
    int h4 = idx4 & 511;
    const int* ps = &g_pair2slot[t * TOPK];
    float4 s = make_float4(0.f, 0.f, 0.f, 0.f);
#pragma unroll
    for (int k = 0; k < TOPK; k++) {
        const float4 v = *(const float4*)&g_dbuf[(size_t)ps[k] * H_DIM + h4 * 4];
        s.x += v.x; s.y += v.y; s.z += v.z; s.w += v.w;
    }
    *(float4*)&out[(size_t)idx4 * 4] = s;
}

// ---------------- launch ----------------
extern "C" void kernel_launch(void* const* d_in, const int* in_sizes, int n_in,
                              void* d_out, int out_size) {
    const float* x  = (const float*)d_in[0];
    const float* gw = (const float*)d_in[1];
    const float* wg = (const float*)d_in[2];
    const float* wu = (const float*)d_in[3];
    const float* wd = (const float*)d_in[4];
    float* out = (float*)d_out;

    int write_ids = (out_size >= T_TOK * H_DIM + P_NUM) ? 1 : 0;

    const int smemA = (2 * A_TILE + 4 * BA_TILE) * 4;   // 73728 B -> 2 CTAs/SM
    const int smemB = (2 * A_TILE + 2 * BB_TILE) * 4;   // 73728 B -> 2 CTAs/SM
    cudaFuncSetAttribute(k_gemmA, cudaFuncAttributeMaxDynamicSharedMemorySize, smemA);
    cudaFuncSetAttribute(k_gemmB, cudaFuncAttributeMaxDynamicSharedMemorySize, smemB);

    k_zero<<<1, 32>>>();
    k_router<<<T_TOK / 8, 256>>>(x, gw, out, write_ids);
    k_scan<<<1, 32>>>();
    k_scatter<<<P_NUM / 256, 256>>>();

    float* wg_t; float* wu_t; float* wd_t; float* x_t;
    cudaGetSymbolAddress((void**)&wg_t, g_wg_t);
    cudaGetSymbolAddress((void**)&wu_t, g_wu_t);
    cudaGetSymbolAddress((void**)&wd_t, g_wd_t);
    cudaGetSymbolAddress((void**)&x_t,  g_x_t);

    // transposing tf32 cvt: wg/wu [E][H][I] -> [E][I][H]; wd [E][I][H] -> [E][H][I]
    {
        dim3 g1(I_DIM / 32, H_DIM / 32, E_NUM);
        k_cvt_t<<<g1, 256>>>(wg, wg_t, H_DIM, I_DIM);
        k_cvt_t<<<g1, 256>>>(wu, wu_t, H_DIM, I_DIM);
        dim3 g2(H_DIM / 32, I_DIM / 32, E_NUM);
        k_cvt_t<<<g2, 256>>>(wd, wd_t, I_DIM, H_DIM);
    }
    k_cvt<<<(T_TOK * H_DIM / 4) / 256, 256>>>(x, x_t);

    dim3 ga(I_DIM / 64, T_TOK / 128, E_NUM);   // (16, 32, 32)
    k_gemmA<<<ga, 256, smemA>>>(x_t, wg_t, wu_t);

    dim3 gb(H_DIM / 128, T_TOK / 128, E_NUM);  // (16, 32, 32)
    k_gemmB<<<gb, 256, smemB>>>(wd_t);

    k_reduce<<<(T_TOK * H_DIM / 4) / 256, 256>>>(out);
}

// round 12
// speedup vs baseline: 1.4249x; 1.1526x over previous
#include <cuda_runtime.h>
#include <cuda_fp16.h>
#include <cstdint>
#include <math.h>

// Problem constants
#define T_TOK 4096
#define H_DIM 2048
#define E_NUM 32
#define I_DIM 1024
#define TOPK  8
#define P_NUM (T_TOK * TOPK)
#define W_ELEMS ((size_t)E_NUM * H_DIM * I_DIM)

// ---------------- scratch ----------------
__device__ int    g_topk_ids[P_NUM];
__device__ float  g_topk_w[P_NUM];
__device__ int    g_cnt[E_NUM];
__device__ int    g_pos[E_NUM];
__device__ int    g_off[E_NUM + 1];
__device__ int    g_slot_token[P_NUM];
__device__ float  g_slot_w[P_NUM];
__device__ int    g_pair2slot[P_NUM];
__device__ __half g_hbuf_h[(size_t)P_NUM * I_DIM];   // fp16 activations (gemmA out)
__device__ float  g_dbuf[(size_t)P_NUM * H_DIM];
// fp16 operands; weights stored TRANSPOSED (n-major)
__device__ __half g_x_h[(size_t)T_TOK * H_DIM];
__device__ __half g_wg_h[W_ELEMS];   // [E][I][H]
__device__ __half g_wu_h[W_ELEMS];   // [E][I][H]
__device__ __half g_wd_h[W_ELEMS];   // [E][H][I]

// ---------------- helpers ----------------
__device__ __forceinline__ void mma16(float c[4], const uint32_t a[4], const uint32_t b[2]) {
    asm volatile(
        "mma.sync.aligned.m16n8k16.row.col.f32.f16.f16.f32 "
        "{%0,%1,%2,%3}, {%4,%5,%6,%7}, {%8,%9}, {%0,%1,%2,%3};\n"
        : "+f"(c[0]), "+f"(c[1]), "+f"(c[2]), "+f"(c[3])
        : "r"(a[0]), "r"(a[1]), "r"(a[2]), "r"(a[3]), "r"(b[0]), "r"(b[1]));
}

__device__ __forceinline__ void ldsm4(uint32_t& r0, uint32_t& r1, uint32_t& r2,
                                      uint32_t& r3, uint32_t addr) {
    asm volatile("ldmatrix.sync.aligned.m8n8.x4.shared.b16 {%0,%1,%2,%3}, [%4];"
                 : "=r"(r0), "=r"(r1), "=r"(r2), "=r"(r3) : "r"(addr));
}

__device__ __forceinline__ void cpa16(uint32_t saddr, const void* g) {
    asm volatile("cp.async.cg.shared.global [%0], [%1], 16;" :: "r"(saddr), "l"(g));
}
#define CP_COMMIT() asm volatile("cp.async.commit_group;")
#define CP_WAIT(N)  asm volatile("cp.async.wait_group %0;" :: "n"(N))

__device__ __forceinline__ float silu(float x) {
    return x * (1.0f / (1.0f + __expf(-x)));
}

// ---------------- kernel 0 ----------------
__global__ void k_zero() {
    if (threadIdx.x < E_NUM) g_cnt[threadIdx.x] = 0;
}

// ---------------- cvt x -> fp16 ----------------
__global__ void k_cvt_h(const float* __restrict__ src, __half* __restrict__ dst) {
    size_t i = ((size_t)blockIdx.x * blockDim.x + threadIdx.x) * 4;
    float4 v = *(const float4*)(src + i);
    __half2 lo = __floats2half2_rn(v.x, v.y);
    __half2 hi = __floats2half2_rn(v.z, v.w);
    *(__half2*)(dst + i)     = lo;
    *(__half2*)(dst + i + 2) = hi;
}

// ---------------- transposing cvt: src [E][R][C] f32 -> dst [E][C][R] fp16 ----------
__global__ __launch_bounds__(256) void k_cvt_t(const float* __restrict__ src,
                                               __half* __restrict__ dst, int R, int C) {
    __shared__ float tile[32][33];
    int e  = blockIdx.z;
    int c0 = blockIdx.x * 32, r0 = blockIdx.y * 32;
    const float* s = src + (size_t)e * R * C;
    __half*      d = dst + (size_t)e * R * C;
    int tx = threadIdx.x & 31, ty = threadIdx.x >> 5;
#pragma unroll
    for (int i = 0; i < 32; i += 8) {
        tile[ty + i][tx] = s[(size_t)(r0 + ty + i) * C + c0 + tx];
    }
    __syncthreads();
#pragma unroll
    for (int i = 0; i < 32; i += 8) {
        d[(size_t)(c0 + ty + i) * R + r0 + tx] = __float2half_rn(tile[tx][ty + i]);
    }
}

// ---------------- kernel 1: router (fp32, exact) ----------------
__global__ __launch_bounds__(256) void k_router(const float* __restrict__ x,
                                                const float* __restrict__ gw,
                                                float* __restrict__ out, int write_ids) {
    __shared__ float s_gw[64 * E_NUM];
    int tid  = threadIdx.x;
    int wid  = tid >> 5, lane = tid & 31;
    int tok  = blockIdx.x * 8 + wid;

    const float* xr = x + (size_t)tok * H_DIM;
    float acc = 0.0f;
    for (int h0 = 0; h0 < H_DIM; h0 += 64) {
#pragma unroll
        for (int i = 0; i < 8; i++) s_gw[tid + i * 256] = gw[h0 * E_NUM + tid + i * 256];
        __syncthreads();
#pragma unroll 16
        for (int hh = 0; hh < 64; hh++) acc += xr[h0 + hh] * s_gw[hh * E_NUM + lane];
        __syncthreads();
    }

    float m = acc;
#pragma unroll
    for (int o = 16; o; o >>= 1) m = fmaxf(m, __shfl_xor_sync(0xffffffffu, m, o));
    float p = expf(acc - m);
    float s = p;
#pragma unroll
    for (int o = 16; o; o >>= 1) s += __shfl_xor_sync(0xffffffffu, s, o);
    float score = p / s;

    float val = score;
    int   ids[TOPK];
    float ws[TOPK];
    float wsum = 0.0f;
#pragma unroll
    for (int j = 0; j < TOPK; j++) {
        float bv = val;
        int   bi = lane;
#pragma unroll
        for (int o = 16; o; o >>= 1) {
            float ov = __shfl_xor_sync(0xffffffffu, bv, o);
            int   oi = __shfl_xor_sync(0xffffffffu, bi, o);
            if (ov > bv || (ov == bv && oi < bi)) { bv = ov; bi = oi; }
        }
        ids[j] = bi; ws[j] = bv; wsum += bv;
        if (lane == bi) val = -1.0f;
    }

    if (lane == 0) {
        float inv = 1.0f / wsum;
#pragma unroll
        for (int j = 0; j < TOPK; j++) {
            g_topk_ids[tok * TOPK + j] = ids[j];
            g_topk_w[tok * TOPK + j]   = ws[j] * inv;
            atomicAdd(&g_cnt[ids[j]], 1);
            if (write_ids)
                out[(size_t)T_TOK * H_DIM + tok * TOPK + j] = (float)ids[j];
        }
    }
}

// ---------------- kernel 2/3 ----------------
__global__ void k_scan() {
    if (threadIdx.x == 0) {
        int acc = 0;
        for (int e = 0; e < E_NUM; e++) { g_off[e] = acc; g_pos[e] = acc; acc += g_cnt[e]; }
        g_off[E_NUM] = acc;
    }
}

__global__ void k_scatter() {
    int pp = blockIdx.x * blockDim.x + threadIdx.x;
    if (pp >= P_NUM) return;
    int e = g_topk_ids[pp];
    int slot = atomicAdd(&g_pos[e], 1);
    g_slot_token[slot] = pp >> 3;
    g_slot_w[slot]     = g_topk_w[pp];
    g_pair2slot[pp]    = slot;
}

// ================= GEMM tiling (units: halves) =================
#define AH_STRIDE 72                 // 64 k-halves + 8 pad (144 B rows, ldsm conflict-free)
#define AH_TILE   (128 * AH_STRIDE)  // 9216 halves / stage
#define BGH_TILE  (64  * AH_STRIDE)  // 4608 halves / stage (gemmA B)
#define BBH_TILE  (128 * AH_STRIDE)  // 9216 halves / stage (gemmB B)

// ================= kernel 4: gate+up GEMM + SwiGLU (fp16 mma) =================
// Block 128M x 64N, BK=64 halves, 2-stage cp.async, one sync/tile, 8 warps, 2 CTAs/SM.
__global__ __launch_bounds__(256, 2) void k_gemmA(const __half* __restrict__ x,
                                                  const __half* __restrict__ wgate,
                                                  const __half* __restrict__ wup) {
    int e   = blockIdx.z;
    int cnt = g_cnt[e];
    int m0  = blockIdx.y * 128;
    if (m0 >= cnt) return;
    int n0   = blockIdx.x * 64;
    int base = g_off[e];
    int tid  = threadIdx.x;

    extern __shared__ __half smem[];
    uint32_t sbase = (uint32_t)__cvta_generic_to_shared(smem);

    __shared__ int s_tok[128];
    if (tid < 128) {
        int m = m0 + tid;
        s_tok[tid] = g_slot_token[base + ((m < cnt) ? m : 0)];
    }
    __syncthreads();

    const __half* wgb = wgate + ((size_t)e * I_DIM + n0) * H_DIM;
    const __half* wub = wup   + ((size_t)e * I_DIM + n0) * H_DIM;

    int c8 = tid & 7, r32 = tid >> 3;   // 8 chunks (16B = 8 halves) per row, 32 rows/pass

    const int NT = H_DIM / 64;  // 32

    auto load_stage = [&](int t, int s) {
        int k0 = t * 64;
        uint32_t ab = sbase + (uint32_t)(s * AH_TILE) * 2u;
        uint32_t gb = sbase + (uint32_t)(2 * AH_TILE + s * BGH_TILE) * 2u;
        uint32_t ub = sbase + (uint32_t)(2 * AH_TILE + 2 * BGH_TILE + s * BGH_TILE) * 2u;
#pragma unroll
        for (int i = 0; i < 4; i++) {
            int r = r32 + i * 32;
            cpa16(ab + (uint32_t)(r * AH_STRIDE + c8 * 8) * 2u,
                  x + (size_t)s_tok[r] * H_DIM + k0 + c8 * 8);
        }
#pragma unroll
        for (int i = 0; i < 2; i++) {
            int r = r32 + i * 32;   // n-row 0..63
            uint32_t so = (uint32_t)(r * AH_STRIDE + c8 * 8) * 2u;
            cpa16(gb + so, wgb + (size_t)r * H_DIM + k0 + c8 * 8);
            cpa16(ub + so, wub + (size_t)r * H_DIM + k0 + c8 * 8);
        }
        CP_COMMIT();
    };

    int wid = tid >> 5, lane = tid & 31;
    int wm = (wid & 3) * 32, wn = (wid >> 2) * 32;
    int gid = lane >> 2, tig = lane & 3;

    // ldmatrix lane addressing
    int a_row  = lane & 15, a_col = (lane >> 4) << 3;            // A: 16 rows x 16 k
    int b_rowo = ((lane >> 4) << 3) + (lane & 7);                // B: 16 n x 16 k
    int b_colo = ((lane >> 3) & 1) << 3;

    float cg[2][4][4], cu[2][4][4];
#pragma unroll
    for (int i = 0; i < 2; i++)
#pragma unroll
        for (int j = 0; j < 4; j++)
#pragma unroll
            for (int q = 0; q < 4; q++) { cg[i][j][q] = 0.0f; cu[i][j][q] = 0.0f; }

    load_stage(0, 0);

    for (int t = 0; t < NT; t++) {
        CP_WAIT(0);
        __syncthreads();
        if (t + 1 < NT) load_stage(t + 1, (t + 1) & 1);

        uint32_t sA = sbase + (uint32_t)((t & 1) * AH_TILE) * 2u;
        uint32_t sG = sbase + (uint32_t)(2 * AH_TILE + (t & 1) * BGH_TILE) * 2u;
        uint32_t sU = sbase + (uint32_t)(2 * AH_TILE + 2 * BGH_TILE + (t & 1) * BGH_TILE) * 2u;

#pragma unroll
        for (int kf = 0; kf < 64; kf += 16) {
            uint32_t a[2][4], bg[4][2], bu[4][2];
#pragma unroll
            for (int mf = 0; mf < 2; mf++) {
                uint32_t addr = sA + (uint32_t)((wm + mf * 16 + a_row) * AH_STRIDE
                                                + kf + a_col) * 2u;
                ldsm4(a[mf][0], a[mf][1], a[mf][2], a[mf][3], addr);
            }
#pragma unroll
            for (int p = 0; p < 2; p++) {
                uint32_t so = (uint32_t)((wn + p * 16 + b_rowo) * AH_STRIDE
                                         + kf + b_colo) * 2u;
                ldsm4(bg[2*p][0], bg[2*p][1], bg[2*p+1][0], bg[2*p+1][1], sG + so);
                ldsm4(bu[2*p][0], bu[2*p][1], bu[2*p+1][0], bu[2*p+1][1], sU + so);
            }
#pragma unroll
            for (int mf = 0; mf < 2; mf++)
#pragma unroll
                for (int nf = 0; nf < 4; nf++) {
                    mma16(cg[mf][nf], a[mf], bg[nf]);
                    mma16(cu[mf][nf], a[mf], bu[nf]);
                }
        }
    }

    // epilogue: h = silu(g)*u -> fp16 hbuf
#pragma unroll
    for (int mf = 0; mf < 2; mf++)
#pragma unroll
        for (int nf = 0; nf < 4; nf++) {
            int col = n0 + wn + nf * 8 + 2 * tig;
            int r1 = wm + mf * 16 + gid;
            int r2 = r1 + 8;
            int m1 = m0 + r1, m2 = m0 + r2;
            if (m1 < cnt) {
                __half2 v = __floats2half2_rn(silu(cg[mf][nf][0]) * cu[mf][nf][0],
                                              silu(cg[mf][nf][1]) * cu[mf][nf][1]);
                *(__half2*)&g_hbuf_h[(size_t)(base + m1) * I_DIM + col] = v;
            }
            if (m2 < cnt) {
                __half2 v = __floats2half2_rn(silu(cg[mf][nf][2]) * cu[mf][nf][2],
                                              silu(cg[mf][nf][3]) * cu[mf][nf][3]);
                *(__half2*)&g_hbuf_h[(size_t)(base + m2) * I_DIM + col] = v;
            }
        }
}

// ================= kernel 5: down GEMM weighted (fp16 mma) =================
// Block 128M x 128N, BK=64 halves, 2-stage cp.async, one sync/tile, 8 warps, 2 CTAs/SM.
__global__ __launch_bounds__(256, 2) void k_gemmB(const __half* __restrict__ wdown) {
    int e   = blockIdx.z;
    int cnt = g_cnt[e];
    int m0  = blockIdx.y * 128;
    if (m0 >= cnt) return;
    int n0   = blockIdx.x * 128;
    int base = g_off[e];
    int tid  = threadIdx.x;

    extern __shared__ __half smem[];
    uint32_t sbase = (uint32_t)__cvta_generic_to_shared(smem);

    const __half* wb = wdown + ((size_t)e * H_DIM + n0) * I_DIM;

    int c8 = tid & 7, r32 = tid >> 3;

    const int NT = I_DIM / 64;  // 16

    auto load_stage = [&](int t, int s) {
        int k0 = t * 64;
        uint32_t ab = sbase + (uint32_t)(s * AH_TILE) * 2u;
        uint32_t bb = sbase + (uint32_t)(2 * AH_TILE + s * BBH_TILE) * 2u;
#pragma unroll
        for (int i = 0; i < 4; i++) {
            int r = r32 + i * 32;
            int m = m0 + r;
            int slot = base + ((m < cnt) ? m : (cnt - 1));
            cpa16(ab + (uint32_t)(r * AH_STRIDE + c8 * 8) * 2u,
                  &g_hbuf_h[(size_t)slot * I_DIM + k0 + c8 * 8]);
        }
#pragma unroll
        for (int i = 0; i < 4; i++) {
            int r = r32 + i * 32;   // n-row 0..127
            cpa16(bb + (uint32_t)(r * AH_STRIDE + c8 * 8) * 2u,
                  wb + (size_t)r * I_DIM + k0 + c8 * 8);
        }
        CP_COMMIT();
    };

    int wid = tid >> 5, lane = tid & 31;
    int wm = (wid & 3) * 32, wn = (wid >> 2) * 64;
    int gid = lane >> 2, tig = lane & 3;

    int a_row  = lane & 15, a_col = (lane >> 4) << 3;
    int b_rowo = ((lane >> 4) << 3) + (lane & 7);
    int b_colo = ((lane >> 3) & 1) << 3;

    float cc[2][8][4];
#pragma unroll
    for (int i = 0; i < 2; i++)
#pragma unroll
        for (int j = 0; j < 8; j++)
#pragma unroll
            for (int q = 0; q < 4; q++) cc[i][j][q] = 0.0f;

    load_stage(0, 0);

    for (int t = 0; t < NT; t++) {
        CP_WAIT(0);
        __syncthreads();
        if (t + 1 < NT) load_stage(t + 1, (t + 1) & 1);

        uint32_t sA = sbase + (uint32_t)((t & 1) * AH_TILE) * 2u;
        uint32_t sB = sbase + (uint32_t)(2 * AH_TILE + (t & 1) * BBH_TILE) * 2u;

#pragma unroll
        for (int kf = 0; kf < 64; kf += 16) {
            uint32_t a[2][4], b[8][2];
#pragma unroll
            for (int mf = 0; mf < 2; mf++) {
                uint32_t addr = sA + (uint32_t)((wm + mf * 16 + a_row) * AH_STRIDE
                                                + kf + a_col) * 2u;
                ldsm4(a[mf][0], a[mf][1], a[mf][2], a[mf][3], addr);
            }
#pragma unroll
            for (int p = 0; p < 4; p++) {
                uint32_t so = (uint32_t)((wn + p * 16 + b_rowo) * AH_STRIDE
                                         + kf + b_colo) * 2u;
                ldsm4(b[2*p][0], b[2*p][1], b[2*p+1][0], b[2*p+1][1], sB + so);
            }
#pragma unroll
            for (int mf = 0; mf < 2; mf++)
#pragma unroll
                for (int nf = 0; nf < 8; nf++) mma16(cc[mf][nf], a[mf], b[nf]);
        }
    }

#pragma unroll
    for (int mf = 0; mf < 2; mf++) {
        int r1 = wm + mf * 16 + gid;
        int r2 = r1 + 8;
        int m1 = m0 + r1, m2 = m0 + r2;
        float w1 = (m1 < cnt) ? g_slot_w[base + m1] : 0.0f;
        float w2 = (m2 < cnt) ? g_slot_w[base + m2] : 0.0f;
#pragma unroll
        for (int nf = 0; nf < 8; nf++) {
            int col = n0 + wn + nf * 8 + 2 * tig;
            if (m1 < cnt) {
                float2 v = make_float2(cc[mf][nf][0] * w1, cc[mf][nf][1] * w1);
                *(float2*)&g_dbuf[(size_t)(base + m1) * H_DIM + col] = v;
            }
            if (m2 < cnt) {
                float2 v = make_float2(cc[mf][nf][2] * w2, cc[mf][nf][3] * w2);
                *(float2*)&g_dbuf[(size_t)(base + m2) * H_DIM + col] = v;
            }
        }
    }
}

// ---------------- kernel 6: combine ----------------
__global__ void k_reduce(float* __restrict__ out) {
    int idx4 = blockIdx.x * blockDim.x + threadIdx.x;
    int t  = idx4 >> 9;
    int h4 = idx4 & 511;
    const int* ps = &g_pair2slot[t * TOPK];
    float4 s = make_float4(0.f, 0.f, 0.f, 0.f);
#pragma unroll
    for (int k = 0; k < TOPK; k++) {
        const float4 v = *(const float4*)&g_dbuf[(size_t)ps[k] * H_DIM + h4 * 4];
        s.x += v.x; s.y += v.y; s.z += v.z; s.w += v.w;
    }
    *(float4*)&out[(size_t)idx4 * 4] = s;
}

// ---------------- launch ----------------
extern "C" void kernel_launch(void* const* d_in, const int* in_sizes, int n_in,
                              void* d_out, int out_size) {
    const float* x  = (const float*)d_in[0];
    const float* gw = (const float*)d_in[1];
    const float* wg = (const float*)d_in[2];
    const float* wu = (const float*)d_in[3];
    const float* wd = (const float*)d_in[4];
    float* out = (float*)d_out;

    int write_ids = (out_size >= T_TOK * H_DIM + P_NUM) ? 1 : 0;

    const int smemA = (2 * AH_TILE + 4 * BGH_TILE) * 2;   // 73728 B -> 2 CTAs/SM
    const int smemB = (2 * AH_TILE + 2 * BBH_TILE) * 2;   // 73728 B -> 2 CTAs/SM
    cudaFuncSetAttribute(k_gemmA, cudaFuncAttributeMaxDynamicSharedMemorySize, smemA);
    cudaFuncSetAttribute(k_gemmB, cudaFuncAttributeMaxDynamicSharedMemorySize, smemB);

    k_zero<<<1, 32>>>();
    k_router<<<T_TOK / 8, 256>>>(x, gw, out, write_ids);
    k_scan<<<1, 32>>>();
    k_scatter<<<P_NUM / 256, 256>>>();

    __half* wg_h; __half* wu_h; __half* wd_h; __half* x_h;
    cudaGetSymbolAddress((void**)&wg_h, g_wg_h);
    cudaGetSymbolAddress((void**)&wu_h, g_wu_h);
    cudaGetSymbolAddress((void**)&wd_h, g_wd_h);
    cudaGetSymbolAddress((void**)&x_h,  g_x_h);

    // transposing fp16 cvt: wg/wu [E][H][I] -> [E][I][H]; wd [E][I][H] -> [E][H][I]
    {
        dim3 g1(I_DIM / 32, H_DIM / 32, E_NUM);
        k_cvt_t<<<g1, 256>>>(wg, wg_h, H_DIM, I_DIM);
        k_cvt_t<<<g1, 256>>>(wu, wu_h, H_DIM, I_DIM);
        dim3 g2(H_DIM / 32, I_DIM / 32, E_NUM);
        k_cvt_t<<<g2, 256>>>(wd, wd_h, I_DIM, H_DIM);
    }
    k_cvt_h<<<(T_TOK * H_DIM / 4) / 256, 256>>>(x, x_h);

    dim3 ga(I_DIM / 64, T_TOK / 128, E_NUM);   // (16, 32, 32)
    k_gemmA<<<ga, 256, smemA>>>(x_h, wg_h, wu_h);

    dim3 gb(H_DIM / 128, T_TOK / 128, E_NUM);  // (16, 32, 32)
    k_gemmB<<<gb, 256, smemB>>>(wd_h);

    k_reduce<<<(T_TOK * H_DIM / 4) / 256, 256>>>(out);
}

// round 13
// speedup vs baseline: 2.0883x; 1.4655x over previous
#include <cuda_runtime.h>
#include <cuda_fp16.h>
#include <cstdint>
#include <math.h>

// Problem constants
#define T_TOK 4096
#define H_DIM 2048
#define E_NUM 32
#define I_DIM 1024
#define TOPK  8
#define P_NUM (T_TOK * TOPK)
#define W_ELEMS ((size_t)E_NUM * H_DIM * I_DIM)

// ---------------- scratch ----------------
__device__ int    g_topk_ids[P_NUM];
__device__ float  g_topk_w[P_NUM];
__device__ int    g_cnt[E_NUM];
__device__ int    g_pos[E_NUM];
__device__ int    g_off[E_NUM + 1];
__device__ int    g_slot_token[P_NUM];
__device__ float  g_slot_w[P_NUM];
__device__ int    g_pair2slot[P_NUM];
__device__ __half g_hbuf_h[(size_t)P_NUM * I_DIM];   // fp16 activations (gemmA out)
__device__ __half g_dbuf_h[(size_t)P_NUM * H_DIM];   // fp16 weighted down-proj
// fp16 operands; weights stored TRANSPOSED (n-major)
__device__ __half g_x_h[(size_t)T_TOK * H_DIM];
__device__ __half g_wg_h[W_ELEMS];   // [E][I][H]
__device__ __half g_wu_h[W_ELEMS];   // [E][I][H]
__device__ __half g_wd_h[W_ELEMS];   // [E][H][I]

// ---------------- helpers ----------------
__device__ __forceinline__ void mma16(float c[4], const uint32_t a[4], const uint32_t b[2]) {
    asm volatile(
        "mma.sync.aligned.m16n8k16.row.col.f32.f16.f16.f32 "
        "{%0,%1,%2,%3}, {%4,%5,%6,%7}, {%8,%9}, {%0,%1,%2,%3};\n"
        : "+f"(c[0]), "+f"(c[1]), "+f"(c[2]), "+f"(c[3])
        : "r"(a[0]), "r"(a[1]), "r"(a[2]), "r"(a[3]), "r"(b[0]), "r"(b[1]));
}

__device__ __forceinline__ void ldsm4(uint32_t& r0, uint32_t& r1, uint32_t& r2,
                                      uint32_t& r3, uint32_t addr) {
    asm volatile("ldmatrix.sync.aligned.m8n8.x4.shared.b16 {%0,%1,%2,%3}, [%4];"
                 : "=r"(r0), "=r"(r1), "=r"(r2), "=r"(r3) : "r"(addr));
}

__device__ __forceinline__ void cpa16(uint32_t saddr, const void* g) {
    asm volatile("cp.async.cg.shared.global [%0], [%1], 16;" :: "r"(saddr), "l"(g));
}
#define CP_COMMIT() asm volatile("cp.async.commit_group;")
#define CP_WAIT(N)  asm volatile("cp.async.wait_group %0;" :: "n"(N))

__device__ __forceinline__ float silu(float x) {
    return x * (1.0f / (1.0f + __expf(-x)));
}

// ---------------- kernel 1: router (fp32 logits) + x->fp16 conversion ----------------
__global__ __launch_bounds__(256) void k_router(const float* __restrict__ x,
                                                const float* __restrict__ gw,
                                                float* __restrict__ out, int write_ids) {
    __shared__ float s_gw[64 * E_NUM];
    int tid  = threadIdx.x;
    int wid  = tid >> 5, lane = tid & 31;
    int tok  = blockIdx.x * 8 + wid;

    const float* xr = x + (size_t)tok * H_DIM;
    float acc = 0.0f;
    for (int h0 = 0; h0 < H_DIM; h0 += 64) {
#pragma unroll
        for (int i = 0; i < 8; i++) s_gw[tid + i * 256] = gw[h0 * E_NUM + tid + i * 256];
        __syncthreads();
#pragma unroll 16
        for (int hh = 0; hh < 64; hh++) acc += xr[h0 + hh] * s_gw[hh * E_NUM + lane];
        __syncthreads();
    }

    // fold x -> fp16 conversion into this kernel (x rows are L2-hot here)
    {
        __half* xh = g_x_h + (size_t)tok * H_DIM;
        for (int h = lane * 2; h < H_DIM; h += 64) {
            float2 v = *(const float2*)&xr[h];
            *(__half2*)&xh[h] = __floats2half2_rn(v.x, v.y);
        }
    }

    float m = acc;
#pragma unroll
    for (int o = 16; o; o >>= 1) m = fmaxf(m, __shfl_xor_sync(0xffffffffu, m, o));
    float p = expf(acc - m);
    float s = p;
#pragma unroll
    for (int o = 16; o; o >>= 1) s += __shfl_xor_sync(0xffffffffu, s, o);
    float score = p / s;

    float val = score;
    int   ids[TOPK];
    float ws[TOPK];
    float wsum = 0.0f;
#pragma unroll
    for (int j = 0; j < TOPK; j++) {
        float bv = val;
        int   bi = lane;
#pragma unroll
        for (int o = 16; o; o >>= 1) {
            float ov = __shfl_xor_sync(0xffffffffu, bv, o);
            int   oi = __shfl_xor_sync(0xffffffffu, bi, o);
            if (ov > bv || (ov == bv && oi < bi)) { bv = ov; bi = oi; }
        }
        ids[j] = bi; ws[j] = bv; wsum += bv;
        if (lane == bi) val = -1.0f;
    }

    if (lane == 0) {
        float inv = 1.0f / wsum;
#pragma unroll
        for (int j = 0; j < TOPK; j++) {
            g_topk_ids[tok * TOPK + j] = ids[j];
            g_topk_w[tok * TOPK + j]   = ws[j] * inv;
            atomicAdd(&g_cnt[ids[j]], 1);
            if (write_ids)
                out[(size_t)T_TOK * H_DIM + tok * TOPK + j] = (float)ids[j];
        }
    }
}

// ---------------- kernel 2: fused scan + scatter (single block) ----------------
__global__ __launch_bounds__(1024) void k_scan_scatter() {
    int tid = threadIdx.x;
    if (tid == 0) {
        int acc = 0;
        for (int e = 0; e < E_NUM; e++) { g_off[e] = acc; g_pos[e] = acc; acc += g_cnt[e]; }
        g_off[E_NUM] = acc;
    }
    __syncthreads();
    for (int pp = tid; pp < P_NUM; pp += 1024) {
        int e = g_topk_ids[pp];
        int slot = atomicAdd(&g_pos[e], 1);
        g_slot_token[slot] = pp >> 3;
        g_slot_w[slot]     = g_topk_w[pp];
        g_pair2slot[pp]    = slot;
    }
}

// ---------------- transposing cvt: src [E][R][C] f32 -> dst [E][C][R] fp16 ----------
__global__ __launch_bounds__(256) void k_cvt_t(const float* __restrict__ src,
                                               __half* __restrict__ dst, int R, int C) {
    __shared__ float tile[32][33];
    int e  = blockIdx.z;
    int c0 = blockIdx.x * 32, r0 = blockIdx.y * 32;
    const float* s = src + (size_t)e * R * C;
    __half*      d = dst + (size_t)e * R * C;
    int tx = threadIdx.x & 31, ty = threadIdx.x >> 5;
#pragma unroll
    for (int i = 0; i < 32; i += 8) {
        tile[ty + i][tx] = s[(size_t)(r0 + ty + i) * C + c0 + tx];
    }
    __syncthreads();
#pragma unroll
    for (int i = 0; i < 32; i += 8) {
        d[(size_t)(c0 + ty + i) * R + r0 + tx] = __float2half_rn(tile[tx][ty + i]);
    }
}

// ================= GEMM tiling (units: halves) =================
#define AH_STRIDE 72                 // 64 k-halves + 8 pad (144 B rows, ldsm conflict-free)
#define AH_TILE   (128 * AH_STRIDE)  // 9216 halves / stage
#define BGH_TILE  (64  * AH_STRIDE)  // 4608 halves / stage (gemmA B)
#define BBH_TILE  (128 * AH_STRIDE)  // 9216 halves / stage (gemmB B)

// ================= kernel 4: gate+up GEMM + SwiGLU (fp16 mma) =================
__global__ __launch_bounds__(256, 2) void k_gemmA(const __half* __restrict__ x,
                                                  const __half* __restrict__ wgate,
                                                  const __half* __restrict__ wup) {
    int e   = blockIdx.z;
    int cnt = g_cnt[e];
    int m0  = blockIdx.y * 128;
    if (m0 >= cnt) return;
    int n0   = blockIdx.x * 64;
    int base = g_off[e];
    int tid  = threadIdx.x;

    extern __shared__ __half smem[];
    uint32_t sbase = (uint32_t)__cvta_generic_to_shared(smem);

    __shared__ int s_tok[128];
    if (tid < 128) {
        int m = m0 + tid;
        s_tok[tid] = g_slot_token[base + ((m < cnt) ? m : 0)];
    }
    __syncthreads();

    const __half* wgb = wgate + ((size_t)e * I_DIM + n0) * H_DIM;
    const __half* wub = wup   + ((size_t)e * I_DIM + n0) * H_DIM;

    int c8 = tid & 7, r32 = tid >> 3;

    const int NT = H_DIM / 64;  // 32

    auto load_stage = [&](int t, int s) {
        int k0 = t * 64;
        uint32_t ab = sbase + (uint32_t)(s * AH_TILE) * 2u;
        uint32_t gb = sbase + (uint32_t)(2 * AH_TILE + s * BGH_TILE) * 2u;
        uint32_t ub = sbase + (uint32_t)(2 * AH_TILE + 2 * BGH_TILE + s * BGH_TILE) * 2u;
#pragma unroll
        for (int i = 0; i < 4; i++) {
            int r = r32 + i * 32;
            cpa16(ab + (uint32_t)(r * AH_STRIDE + c8 * 8) * 2u,
                  x + (size_t)s_tok[r] * H_DIM + k0 + c8 * 8);
        }
#pragma unroll
        for (int i = 0; i < 2; i++) {
            int r = r32 + i * 32;
            uint32_t so = (uint32_t)(r * AH_STRIDE + c8 * 8) * 2u;
            cpa16(gb + so, wgb + (size_t)r * H_DIM + k0 + c8 * 8);
            cpa16(ub + so, wub + (size_t)r * H_DIM + k0 + c8 * 8);
        }
        CP_COMMIT();
    };

    int wid = tid >> 5, lane = tid & 31;
    int wm = (wid & 3) * 32, wn = (wid >> 2) * 32;
    int gid = lane >> 2, tig = lane & 3;

    int a_row  = lane & 15, a_col = (lane >> 4) << 3;
    int b_rowo = ((lane >> 4) << 3) + (lane & 7);
    int b_colo = ((lane >> 3) & 1) << 3;

    float cg[2][4][4], cu[2][4][4];
#pragma unroll
    for (int i = 0; i < 2; i++)
#pragma unroll
        for (int j = 0; j < 4; j++)
#pragma unroll
            for (int q = 0; q < 4; q++) { cg[i][j][q] = 0.0f; cu[i][j][q] = 0.0f; }

    load_stage(0, 0);

    for (int t = 0; t < NT; t++) {
        CP_WAIT(0);
        __syncthreads();
        if (t + 1 < NT) load_stage(t + 1, (t + 1) & 1);

        uint32_t sA = sbase + (uint32_t)((t & 1) * AH_TILE) * 2u;
        uint32_t sG = sbase + (uint32_t)(2 * AH_TILE + (t & 1) * BGH_TILE) * 2u;
        uint32_t sU = sbase + (uint32_t)(2 * AH_TILE + 2 * BGH_TILE + (t & 1) * BGH_TILE) * 2u;

#pragma unroll
        for (int kf = 0; kf < 64; kf += 16) {
            uint32_t a[2][4], bg[4][2], bu[4][2];
#pragma unroll
            for (int mf = 0; mf < 2; mf++) {
                uint32_t addr = sA + (uint32_t)((wm + mf * 16 + a_row) * AH_STRIDE
                                                + kf + a_col) * 2u;
                ldsm4(a[mf][0], a[mf][1], a[mf][2], a[mf][3], addr);
            }
#pragma unroll
            for (int p = 0; p < 2; p++) {
                uint32_t so = (uint32_t)((wn + p * 16 + b_rowo) * AH_STRIDE
                                         + kf + b_colo) * 2u;
                ldsm4(bg[2*p][0], bg[2*p][1], bg[2*p+1][0], bg[2*p+1][1], sG + so);
                ldsm4(bu[2*p][0], bu[2*p][1], bu[2*p+1][0], bu[2*p+1][1], sU + so);
            }
#pragma unroll
            for (int mf = 0; mf < 2; mf++)
#pragma unroll
                for (int nf = 0; nf < 4; nf++) {
                    mma16(cg[mf][nf], a[mf], bg[nf]);
                    mma16(cu[mf][nf], a[mf], bu[nf]);
                }
        }
    }

    // epilogue: h = silu(g)*u -> fp16 hbuf
#pragma unroll
    for (int mf = 0; mf < 2; mf++)
#pragma unroll
        for (int nf = 0; nf < 4; nf++) {
            int col = n0 + wn + nf * 8 + 2 * tig;
            int r1 = wm + mf * 16 + gid;
            int r2 = r1 + 8;
            int m1 = m0 + r1, m2 = m0 + r2;
            if (m1 < cnt) {
                __half2 v = __floats2half2_rn(silu(cg[mf][nf][0]) * cu[mf][nf][0],
                                              silu(cg[mf][nf][1]) * cu[mf][nf][1]);
                *(__half2*)&g_hbuf_h[(size_t)(base + m1) * I_DIM + col] = v;
            }
            if (m2 < cnt) {
                __half2 v = __floats2half2_rn(silu(cg[mf][nf][2]) * cu[mf][nf][2],
                                              silu(cg[mf][nf][3]) * cu[mf][nf][3]);
                *(__half2*)&g_hbuf_h[(size_t)(base + m2) * I_DIM + col] = v;
            }
        }
}

// ================= kernel 5: down GEMM weighted (fp16 mma, fp16 out) =================
__global__ __launch_bounds__(256, 2) void k_gemmB(const __half* __restrict__ wdown) {
    int e   = blockIdx.z;
    int cnt = g_cnt[e];
    int m0  = blockIdx.y * 128;
    if (m0 >= cnt) return;
    int n0   = blockIdx.x * 128;
    int base = g_off[e];
    int tid  = threadIdx.x;

    extern __shared__ __half smem[];
    uint32_t sbase = (uint32_t)__cvta_generic_to_shared(smem);

    const __half* wb = wdown + ((size_t)e * H_DIM + n0) * I_DIM;

    int c8 = tid & 7, r32 = tid >> 3;

    const int NT = I_DIM / 64;  // 16

    auto load_stage = [&](int t, int s) {
        int k0 = t * 64;
        uint32_t ab = sbase + (uint32_t)(s * AH_TILE) * 2u;
        uint32_t bb = sbase + (uint32_t)(2 * AH_TILE + s * BBH_TILE) * 2u;
#pragma unroll
        for (int i = 0; i < 4; i++) {
            int r = r32 + i * 32;
            int m = m0 + r;
            int slot = base + ((m < cnt) ? m : (cnt - 1));
            cpa16(ab + (uint32_t)(r * AH_STRIDE + c8 * 8) * 2u,
                  &g_hbuf_h[(size_t)slot * I_DIM + k0 + c8 * 8]);
        }
#pragma unroll
        for (int i = 0; i < 4; i++) {
            int r = r32 + i * 32;
            cpa16(bb + (uint32_t)(r * AH_STRIDE + c8 * 8) * 2u,
                  wb + (size_t)r * I_DIM + k0 + c8 * 8);
        }
        CP_COMMIT();
    };

    int wid = tid >> 5, lane = tid & 31;
    int wm = (wid & 3) * 32, wn = (wid >> 2) * 64;
    int gid = lane >> 2, tig = lane & 3;

    int a_row  = lane & 15, a_col = (lane >> 4) << 3;
    int b_rowo = ((lane >> 4) << 3) + (lane & 7);
    int b_colo = ((lane >> 3) & 1) << 3;

    float cc[2][8][4];
#pragma unroll
    for (int i = 0; i < 2; i++)
#pragma unroll
        for (int j = 0; j < 8; j++)
#pragma unroll
            for (int q = 0; q < 4; q++) cc[i][j][q] = 0.0f;

    load_stage(0, 0);

    for (int t = 0; t < NT; t++) {
        CP_WAIT(0);
        __syncthreads();
        if (t + 1 < NT) load_stage(t + 1, (t + 1) & 1);

        uint32_t sA = sbase + (uint32_t)((t & 1) * AH_TILE) * 2u;
        uint32_t sB = sbase + (uint32_t)(2 * AH_TILE + (t & 1) * BBH_TILE) * 2u;

#pragma unroll
        for (int kf = 0; kf < 64; kf += 16) {
            uint32_t a[2][4], b[8][2];
#pragma unroll
            for (int mf = 0; mf < 2; mf++) {
                uint32_t addr = sA + (uint32_t)((wm + mf * 16 + a_row) * AH_STRIDE
                                                + kf + a_col) * 2u;
                ldsm4(a[mf][0], a[mf][1], a[mf][2], a[mf][3], addr);
            }
#pragma unroll
            for (int p = 0; p < 4; p++) {
                uint32_t so = (uint32_t)((wn + p * 16 + b_rowo) * AH_STRIDE
                                         + kf + b_colo) * 2u;
                ldsm4(b[2*p][0], b[2*p][1], b[2*p+1][0], b[2*p+1][1], sB + so);
            }
#pragma unroll
            for (int mf = 0; mf < 2; mf++)
#pragma unroll
                for (int nf = 0; nf < 8; nf++) mma16(cc[mf][nf], a[mf], b[nf]);
        }
    }

#pragma unroll
    for (int mf = 0; mf < 2; mf++) {
        int r1 = wm + mf * 16 + gid;
        int r2 = r1 + 8;
        int m1 = m0 + r1, m2 = m0 + r2;
        float w1 = (m1 < cnt) ? g_slot_w[base + m1] : 0.0f;
        float w2 = (m2 < cnt) ? g_slot_w[base + m2] : 0.0f;
#pragma unroll
        for (int nf = 0; nf < 8; nf++) {
            int col = n0 + wn + nf * 8 + 2 * tig;
            if (m1 < cnt) {
                __half2 v = __floats2half2_rn(cc[mf][nf][0] * w1, cc[mf][nf][1] * w1);
                *(__half2*)&g_dbuf_h[(size_t)(base + m1) * H_DIM + col] = v;
            }
            if (m2 < cnt) {
                __half2 v = __floats2half2_rn(cc[mf][nf][2] * w2, cc[mf][nf][3] * w2);
                *(__half2*)&g_dbuf_h[(size_t)(base + m2) * H_DIM + col] = v;
            }
        }
    }
}

// ---------------- kernel 6: combine (fp16 in, fp32 out) ----------------
__global__ void k_reduce(float* __restrict__ out) {
    int idx4 = blockIdx.x * blockDim.x + threadIdx.x;  // over T*H/4
    int t  = idx4 >> 9;
    int h4 = idx4 & 511;
    const int* ps = &g_pair2slot[t * TOPK];
    float4 s = make_float4(0.f, 0.f, 0.f, 0.f);
#pragma unroll
    for (int k = 0; k < TOPK; k++) {
        uint2 raw = *(const uint2*)&g_dbuf_h[(size_t)ps[k] * H_DIM + h4 * 4];
        __half2 p0 = *(__half2*)&raw.x;
        __half2 p1 = *(__half2*)&raw.y;
        float2 f0 = __half22float2(p0);
        float2 f1 = __half22float2(p1);
        s.x += f0.x; s.y += f0.y; s.z += f1.x; s.w += f1.y;
    }
    *(float4*)&out[(size_t)idx4 * 4] = s;
}

// ---------------- launch ----------------
extern "C" void kernel_launch(void* const* d_in, const int* in_sizes, int n_in,
                              void* d_out, int out_size) {
    const float* x  = (const float*)d_in[0];
    const float* gw = (const float*)d_in[1];
    const float* wg = (const float*)d_in[2];
    const float* wu = (const float*)d_in[3];
    const float* wd = (const float*)d_in[4];
    float* out = (float*)d_out;

    int write_ids = (out_size >= T_TOK * H_DIM + P_NUM) ? 1 : 0;

    const int smemA = (2 * AH_TILE + 4 * BGH_TILE) * 2;   // 73728 B -> 2 CTAs/SM
    const int smemB = (2 * AH_TILE + 2 * BBH_TILE) * 2;   // 73728 B -> 2 CTAs/SM
    cudaFuncSetAttribute(k_gemmA, cudaFuncAttributeMaxDynamicSharedMemorySize, smemA);
    cudaFuncSetAttribute(k_gemmB, cudaFuncAttributeMaxDynamicSharedMemorySize, smemB);

    // zero expert counters via memset (not a kernel launch)
    int* cnt_p;
    cudaGetSymbolAddress((void**)&cnt_p, g_cnt);
    cudaMemsetAsync(cnt_p, 0, E_NUM * sizeof(int));

    k_router<<<T_TOK / 8, 256>>>(x, gw, out, write_ids);       // launch 1
    k_scan_scatter<<<1, 1024>>>();                             // launch 2

    __half* wg_h; __half* wu_h; __half* wd_h; __half* x_h;
    cudaGetSymbolAddress((void**)&wg_h, g_wg_h);
    cudaGetSymbolAddress((void**)&wu_h, g_wu_h);
    cudaGetSymbolAddress((void**)&wd_h, g_wd_h);
    cudaGetSymbolAddress((void**)&x_h,  g_x_h);

    {
        dim3 g1(I_DIM / 32, H_DIM / 32, E_NUM);
        k_cvt_t<<<g1, 256>>>(wg, wg_h, H_DIM, I_DIM);          // launch 3
        k_cvt_t<<<g1, 256>>>(wu, wu_h, H_DIM, I_DIM);          // launch 4
        dim3 g2(H_DIM / 32, I_DIM / 32, E_NUM);
        k_cvt_t<<<g2, 256>>>(wd, wd_h, I_DIM, H_DIM);          // launch 5
    }

    dim3 ga(I_DIM / 64, T_TOK / 128, E_NUM);   // (16, 32, 32)
    k_gemmA<<<ga, 256, smemA>>>(x_h, wg_h, wu_h);              // launch 6 (ncu -s 5 target)

    dim3 gb(H_DIM / 128, T_TOK / 128, E_NUM);  // (16, 32, 32)
    k_gemmB<<<gb, 256, smemB>>>(wd_h);                         // launch 7

    k_reduce<<<(T_TOK * H_DIM / 4) / 256, 256>>>(out);         // launch 8
}

// round 14
// speedup vs baseline: 2.0889x; 1.0003x over previous
#include <cuda_runtime.h>
#include <cuda_fp16.h>
#include <cstdint>
#include <math.h>

// Problem constants
#define T_TOK 4096
#define H_DIM 2048
#define E_NUM 32
#define I_DIM 1024
#define TOPK  8
#define P_NUM (T_TOK * TOPK)
#define W_ELEMS ((size_t)E_NUM * H_DIM * I_DIM)

// ---------------- scratch ----------------
__device__ int    g_topk_ids[P_NUM];
__device__ float  g_topk_w[P_NUM];
__device__ int    g_cnt[E_NUM];
__device__ int    g_pos[E_NUM];
__device__ int    g_off[E_NUM + 1];
__device__ int    g_slot_token[P_NUM];
__device__ float  g_slot_w[P_NUM];
__device__ int    g_pair2slot[P_NUM];
__device__ __half g_hbuf_h[(size_t)P_NUM * I_DIM];   // fp16 activations (gemmA out)
__device__ __half g_dbuf_h[(size_t)P_NUM * H_DIM];   // fp16 weighted down-proj
// fp16 operands; weights stored TRANSPOSED (n-major)
__device__ __half g_x_h[(size_t)T_TOK * H_DIM];
__device__ __half g_wg_h[W_ELEMS];   // [E][I][H]
__device__ __half g_wu_h[W_ELEMS];   // [E][I][H]
__device__ __half g_wd_h[W_ELEMS];   // [E][H][I]

// ---------------- helpers ----------------
__device__ __forceinline__ void mma16(float c[4], const uint32_t a[4], const uint32_t b[2]) {
    asm volatile(
        "mma.sync.aligned.m16n8k16.row.col.f32.f16.f16.f32 "
        "{%0,%1,%2,%3}, {%4,%5,%6,%7}, {%8,%9}, {%0,%1,%2,%3};\n"
        : "+f"(c[0]), "+f"(c[1]), "+f"(c[2]), "+f"(c[3])
        : "r"(a[0]), "r"(a[1]), "r"(a[2]), "r"(a[3]), "r"(b[0]), "r"(b[1]));
}

__device__ __forceinline__ void ldsm4(uint32_t& r0, uint32_t& r1, uint32_t& r2,
                                      uint32_t& r3, uint32_t addr) {
    asm volatile("ldmatrix.sync.aligned.m8n8.x4.shared.b16 {%0,%1,%2,%3}, [%4];"
                 : "=r"(r0), "=r"(r1), "=r"(r2), "=r"(r3) : "r"(addr));
}

__device__ __forceinline__ void cpa16(uint32_t saddr, const void* g) {
    asm volatile("cp.async.cg.shared.global [%0], [%1], 16;" :: "r"(saddr), "l"(g));
}
#define CP_COMMIT() asm volatile("cp.async.commit_group;")
#define CP_WAIT(N)  asm volatile("cp.async.wait_group %0;" :: "n"(N))

__device__ __forceinline__ float silu(float x) {
    return x * (1.0f / (1.0f + __expf(-x)));
}

// pack 4 floats -> 4 halves (uint2)
__device__ __forceinline__ uint2 pack4h(float a, float b, float c, float d) {
    __half2 lo = __floats2half2_rn(a, b);
    __half2 hi = __floats2half2_rn(c, d);
    uint2 r;
    r.x = *(uint32_t*)&lo;
    r.y = *(uint32_t*)&hi;
    return r;
}

// ---------------- kernel 1: router (fp32 logits) + x->fp16 conversion ----------------
__global__ __launch_bounds__(256) void k_router(const float* __restrict__ x,
                                                const float* __restrict__ gw,
                                                float* __restrict__ out, int write_ids) {
    __shared__ float s_gw[64 * E_NUM];
    int tid  = threadIdx.x;
    int wid  = tid >> 5, lane = tid & 31;
    int tok  = blockIdx.x * 8 + wid;

    const float* xr = x + (size_t)tok * H_DIM;
    float acc = 0.0f;
    for (int h0 = 0; h0 < H_DIM; h0 += 64) {
#pragma unroll
        for (int i = 0; i < 8; i++) s_gw[tid + i * 256] = gw[h0 * E_NUM + tid + i * 256];
        __syncthreads();
#pragma unroll 16
        for (int hh = 0; hh < 64; hh++) acc += xr[h0 + hh] * s_gw[hh * E_NUM + lane];
        __syncthreads();
    }

    // fold x -> fp16 conversion into this kernel (x rows are L2-hot here)
    {
        __half* xh = g_x_h + (size_t)tok * H_DIM;
        for (int h = lane * 4; h < H_DIM; h += 128) {
            float4 v = *(const float4*)&xr[h];
            *(uint2*)&xh[h] = pack4h(v.x, v.y, v.z, v.w);
        }
    }

    float m = acc;
#pragma unroll
    for (int o = 16; o; o >>= 1) m = fmaxf(m, __shfl_xor_sync(0xffffffffu, m, o));
    float p = expf(acc - m);
    float s = p;
#pragma unroll
    for (int o = 16; o; o >>= 1) s += __shfl_xor_sync(0xffffffffu, s, o);
    float score = p / s;

    float val = score;
    int   ids[TOPK];
    float ws[TOPK];
    float wsum = 0.0f;
#pragma unroll
    for (int j = 0; j < TOPK; j++) {
        float bv = val;
        int   bi = lane;
#pragma unroll
        for (int o = 16; o; o >>= 1) {
            float ov = __shfl_xor_sync(0xffffffffu, bv, o);
            int   oi = __shfl_xor_sync(0xffffffffu, bi, o);
            if (ov > bv || (ov == bv && oi < bi)) { bv = ov; bi = oi; }
        }
        ids[j] = bi; ws[j] = bv; wsum += bv;
        if (lane == bi) val = -1.0f;
    }

    if (lane == 0) {
        float inv = 1.0f / wsum;
#pragma unroll
        for (int j = 0; j < TOPK; j++) {
            g_topk_ids[tok * TOPK + j] = ids[j];
            g_topk_w[tok * TOPK + j]   = ws[j] * inv;
            atomicAdd(&g_cnt[ids[j]], 1);
            if (write_ids)
                out[(size_t)T_TOK * H_DIM + tok * TOPK + j] = (float)ids[j];
        }
    }
}

// ---------------- kernel 2: fused scan + scatter (single block) ----------------
__global__ __launch_bounds__(1024) void k_scan_scatter() {
    int tid = threadIdx.x;
    if (tid == 0) {
        int acc = 0;
        for (int e = 0; e < E_NUM; e++) { g_off[e] = acc; g_pos[e] = acc; acc += g_cnt[e]; }
        g_off[E_NUM] = acc;
    }
    __syncthreads();
    for (int pp = tid; pp < P_NUM; pp += 1024) {
        int e = g_topk_ids[pp];
        int slot = atomicAdd(&g_pos[e], 1);
        g_slot_token[slot] = pp >> 3;
        g_slot_w[slot]     = g_topk_w[pp];
        g_pair2slot[pp]    = slot;
    }
}

// ---------------- vectorized transposing cvt (dual tensor): [E][R][C] f32 -> [E][C][R] fp16
// 32x32 tile; loads float4, stores 4 halves (8B).
__global__ __launch_bounds__(256) void k_cvt_t2(const float* __restrict__ s1,
                                                const float* __restrict__ s2,
                                                __half* __restrict__ d1,
                                                __half* __restrict__ d2, int R, int C) {
    __shared__ float t1[32][36];
    __shared__ float t2[32][36];
    int e  = blockIdx.z;
    int c0 = blockIdx.x * 32, r0 = blockIdx.y * 32;
    size_t eo = (size_t)e * R * C;
    int tid = threadIdx.x;
    int lr = tid >> 3, lc = (tid & 7) * 4;   // load: 32 rows x 8 float4
    {
        float4 v1 = *(const float4*)&s1[eo + (size_t)(r0 + lr) * C + c0 + lc];
        float4 v2 = *(const float4*)&s2[eo + (size_t)(r0 + lr) * C + c0 + lc];
        *(float4*)&t1[lr][lc] = v1;
        *(float4*)&t2[lr][lc] = v2;
    }
    __syncthreads();
    int sc = tid >> 3, sr = (tid & 7) * 4;   // store: 32 c-rows x 8 groups of 4 r
    {
        uint2 v1 = pack4h(t1[sr][sc], t1[sr+1][sc], t1[sr+2][sc], t1[sr+3][sc]);
        uint2 v2 = pack4h(t2[sr][sc], t2[sr+1][sc], t2[sr+2][sc], t2[sr+3][sc]);
        *(uint2*)&d1[eo + (size_t)(c0 + sc) * R + r0 + sr] = v1;
        *(uint2*)&d2[eo + (size_t)(c0 + sc) * R + r0 + sr] = v2;
    }
}

// single-tensor variant (wd)
__global__ __launch_bounds__(256) void k_cvt_t1(const float* __restrict__ s1,
                                                __half* __restrict__ d1, int R, int C) {
    __shared__ float t1[32][36];
    int e  = blockIdx.z;
    int c0 = blockIdx.x * 32, r0 = blockIdx.y * 32;
    size_t eo = (size_t)e * R * C;
    int tid = threadIdx.x;
    int lr = tid >> 3, lc = (tid & 7) * 4;
    *(float4*)&t1[lr][lc] = *(const float4*)&s1[eo + (size_t)(r0 + lr) * C + c0 + lc];
    __syncthreads();
    int sc = tid >> 3, sr = (tid & 7) * 4;
    uint2 v1 = pack4h(t1[sr][sc], t1[sr+1][sc], t1[sr+2][sc], t1[sr+3][sc]);
    *(uint2*)&d1[eo + (size_t)(c0 + sc) * R + r0 + sr] = v1;
}

// ================= GEMM tiling (units: halves) =================
#define AH_STRIDE 72                 // 64 k-halves + 8 pad (144 B rows, ldsm conflict-free)
#define AH_TILE   (128 * AH_STRIDE)  // 9216 halves / stage
#define BGH_TILE  (64  * AH_STRIDE)  // 4608 halves / stage (gemmA B)
#define BBH_TILE  (128 * AH_STRIDE)  // 9216 halves / stage (gemmB B)

// ================= kernel 4: gate+up GEMM + SwiGLU (fp16 mma) =================
__global__ __launch_bounds__(256, 2) void k_gemmA(const __half* __restrict__ x,
                                                  const __half* __restrict__ wgate,
                                                  const __half* __restrict__ wup) {
    int e   = blockIdx.z;
    int cnt = g_cnt[e];
    int m0  = blockIdx.y * 128;
    if (m0 >= cnt) return;
    int n0   = blockIdx.x * 64;
    int base = g_off[e];
    int tid  = threadIdx.x;

    extern __shared__ __half smem[];
    uint32_t sbase = (uint32_t)__cvta_generic_to_shared(smem);

    __shared__ int s_tok[128];
    if (tid < 128) {
        int m = m0 + tid;
        s_tok[tid] = g_slot_token[base + ((m < cnt) ? m : 0)];
    }
    __syncthreads();

    const __half* wgb = wgate + ((size_t)e * I_DIM + n0) * H_DIM;
    const __half* wub = wup   + ((size_t)e * I_DIM + n0) * H_DIM;

    int c8 = tid & 7, r32 = tid >> 3;

    const int NT = H_DIM / 64;  // 32

    auto load_stage = [&](int t, int s) {
        int k0 = t * 64;
        uint32_t ab = sbase + (uint32_t)(s * AH_TILE) * 2u;
        uint32_t gb = sbase + (uint32_t)(2 * AH_TILE + s * BGH_TILE) * 2u;
        uint32_t ub = sbase + (uint32_t)(2 * AH_TILE + 2 * BGH_TILE + s * BGH_TILE) * 2u;
#pragma unroll
        for (int i = 0; i < 4; i++) {
            int r = r32 + i * 32;
            cpa16(ab + (uint32_t)(r * AH_STRIDE + c8 * 8) * 2u,
                  x + (size_t)s_tok[r] * H_DIM + k0 + c8 * 8);
        }
#pragma unroll
        for (int i = 0; i < 2; i++) {
            int r = r32 + i * 32;
            uint32_t so = (uint32_t)(r * AH_STRIDE + c8 * 8) * 2u;
            cpa16(gb + so, wgb + (size_t)r * H_DIM + k0 + c8 * 8);
            cpa16(ub + so, wub + (size_t)r * H_DIM + k0 + c8 * 8);
        }
        CP_COMMIT();
    };

    int wid = tid >> 5, lane = tid & 31;
    int wm = (wid & 3) * 32, wn = (wid >> 2) * 32;
    int gid = lane >> 2, tig = lane & 3;

    int a_row  = lane & 15, a_col = (lane >> 4) << 3;
    int b_rowo = ((lane >> 4) << 3) + (lane & 7);
    int b_colo = ((lane >> 3) & 1) << 3;

    float cg[2][4][4], cu[2][4][4];
#pragma unroll
    for (int i = 0; i < 2; i++)
#pragma unroll
        for (int j = 0; j < 4; j++)
#pragma unroll
            for (int q = 0; q < 4; q++) { cg[i][j][q] = 0.0f; cu[i][j][q] = 0.0f; }

    load_stage(0, 0);

    for (int t = 0; t < NT; t++) {
        CP_WAIT(0);
        __syncthreads();
        if (t + 1 < NT) load_stage(t + 1, (t + 1) & 1);

        uint32_t sA = sbase + (uint32_t)((t & 1) * AH_TILE) * 2u;
        uint32_t sG = sbase + (uint32_t)(2 * AH_TILE + (t & 1) * BGH_TILE) * 2u;
        uint32_t sU = sbase + (uint32_t)(2 * AH_TILE + 2 * BGH_TILE + (t & 1) * BGH_TILE) * 2u;

#pragma unroll
        for (int kf = 0; kf < 64; kf += 16) {
            uint32_t a[2][4], bg[4][2], bu[4][2];
#pragma unroll
            for (int mf = 0; mf < 2; mf++) {
                uint32_t addr = sA + (uint32_t)((wm + mf * 16 + a_row) * AH_STRIDE
                                                + kf + a_col) * 2u;
                ldsm4(a[mf][0], a[mf][1], a[mf][2], a[mf][3], addr);
            }
#pragma unroll
            for (int p = 0; p < 2; p++) {
                uint32_t so = (uint32_t)((wn + p * 16 + b_rowo) * AH_STRIDE
                                         + kf + b_colo) * 2u;
                ldsm4(bg[2*p][0], bg[2*p][1], bg[2*p+1][0], bg[2*p+1][1], sG + so);
                ldsm4(bu[2*p][0], bu[2*p][1], bu[2*p+1][0], bu[2*p+1][1], sU + so);
            }
#pragma unroll
            for (int mf = 0; mf < 2; mf++)
#pragma unroll
                for (int nf = 0; nf < 4; nf++) {
                    mma16(cg[mf][nf], a[mf], bg[nf]);
                    mma16(cu[mf][nf], a[mf], bu[nf]);
                }
        }
    }

    // epilogue: h = silu(g)*u -> fp16 hbuf
#pragma unroll
    for (int mf = 0; mf < 2; mf++)
#pragma unroll
        for (int nf = 0; nf < 4; nf++) {
            int col = n0 + wn + nf * 8 + 2 * tig;
            int r1 = wm + mf * 16 + gid;
            int r2 = r1 + 8;
            int m1 = m0 + r1, m2 = m0 + r2;
            if (m1 < cnt) {
                __half2 v = __floats2half2_rn(silu(cg[mf][nf][0]) * cu[mf][nf][0],
                                              silu(cg[mf][nf][1]) * cu[mf][nf][1]);
                *(__half2*)&g_hbuf_h[(size_t)(base + m1) * I_DIM + col] = v;
            }
            if (m2 < cnt) {
                __half2 v = __floats2half2_rn(silu(cg[mf][nf][2]) * cu[mf][nf][2],
                                              silu(cg[mf][nf][3]) * cu[mf][nf][3]);
                *(__half2*)&g_hbuf_h[(size_t)(base + m2) * I_DIM + col] = v;
            }
        }
}

// ================= kernel 5: down GEMM weighted (fp16 mma, fp16 out) =================
__global__ __launch_bounds__(256, 2) void k_gemmB(const __half* __restrict__ wdown) {
    int e   = blockIdx.z;
    int cnt = g_cnt[e];
    int m0  = blockIdx.y * 128;
    if (m0 >= cnt) return;
    int n0   = blockIdx.x * 128;
    int base = g_off[e];
    int tid  = threadIdx.x;

    extern __shared__ __half smem[];
    uint32_t sbase = (uint32_t)__cvta_generic_to_shared(smem);

    const __half* wb = wdown + ((size_t)e * H_DIM + n0) * I_DIM;

    int c8 = tid & 7, r32 = tid >> 3;

    const int NT = I_DIM / 64;  // 16

    auto load_stage = [&](int t, int s) {
        int k0 = t * 64;
        uint32_t ab = sbase + (uint32_t)(s * AH_TILE) * 2u;
        uint32_t bb = sbase + (uint32_t)(2 * AH_TILE + s * BBH_TILE) * 2u;
#pragma unroll
        for (int i = 0; i < 4; i++) {
            int r = r32 + i * 32;
            int m = m0 + r;
            int slot = base + ((m < cnt) ? m : (cnt - 1));
            cpa16(ab + (uint32_t)(r * AH_STRIDE + c8 * 8) * 2u,
                  &g_hbuf_h[(size_t)slot * I_DIM + k0 + c8 * 8]);
        }
#pragma unroll
        for (int i = 0; i < 4; i++) {
            int r = r32 + i * 32;
            cpa16(bb + (uint32_t)(r * AH_STRIDE + c8 * 8) * 2u,
                  wb + (size_t)r * I_DIM + k0 + c8 * 8);
        }
        CP_COMMIT();
    };

    int wid = tid >> 5, lane = tid & 31;
    int wm = (wid & 3) * 32, wn = (wid >> 2) * 64;
    int gid = lane >> 2, tig = lane & 3;

    int a_row  = lane & 15, a_col = (lane >> 4) << 3;
    int b_rowo = ((lane >> 4) << 3) + (lane & 7);
    int b_colo = ((lane >> 3) & 1) << 3;

    float cc[2][8][4];
#pragma unroll
    for (int i = 0; i < 2; i++)
#pragma unroll
        for (int j = 0; j < 8; j++)
#pragma unroll
            for (int q = 0; q < 4; q++) cc[i][j][q] = 0.0f;

    load_stage(0, 0);

    for (int t = 0; t < NT; t++) {
        CP_WAIT(0);
        __syncthreads();
        if (t + 1 < NT) load_stage(t + 1, (t + 1) & 1);

        uint32_t sA = sbase + (uint32_t)((t & 1) * AH_TILE) * 2u;
        uint32_t sB = sbase + (uint32_t)(2 * AH_TILE + (t & 1) * BBH_TILE) * 2u;

#pragma unroll
        for (int kf = 0; kf < 64; kf += 16) {
            uint32_t a[2][4], b[8][2];
#pragma unroll
            for (int mf = 0; mf < 2; mf++) {
                uint32_t addr = sA + (uint32_t)((wm + mf * 16 + a_row) * AH_STRIDE
                                                + kf + a_col) * 2u;
                ldsm4(a[mf][0], a[mf][1], a[mf][2], a[mf][3], addr);
            }
#pragma unroll
            for (int p = 0; p < 4; p++) {
                uint32_t so = (uint32_t)((wn + p * 16 + b_rowo) * AH_STRIDE
                                         + kf + b_colo) * 2u;
                ldsm4(b[2*p][0], b[2*p][1], b[2*p+1][0], b[2*p+1][1], sB + so);
            }
#pragma unroll
            for (int mf = 0; mf < 2; mf++)
#pragma unroll
                for (int nf = 0; nf < 8; nf++) mma16(cc[mf][nf], a[mf], b[nf]);
        }
    }

#pragma unroll
    for (int mf = 0; mf < 2; mf++) {
        int r1 = wm + mf * 16 + gid;
        int r2 = r1 + 8;
        int m1 = m0 + r1, m2 = m0 + r2;
        float w1 = (m1 < cnt) ? g_slot_w[base + m1] : 0.0f;
        float w2 = (m2 < cnt) ? g_slot_w[base + m2] : 0.0f;
#pragma unroll
        for (int nf = 0; nf < 8; nf++) {
            int col = n0 + wn + nf * 8 + 2 * tig;
            if (m1 < cnt) {
                __half2 v = __floats2half2_rn(cc[mf][nf][0] * w1, cc[mf][nf][1] * w1);
                *(__half2*)&g_dbuf_h[(size_t)(base + m1) * H_DIM + col] = v;
            }
            if (m2 < cnt) {
                __half2 v = __floats2half2_rn(cc[mf][nf][2] * w2, cc[mf][nf][3] * w2);
                *(__half2*)&g_dbuf_h[(size_t)(base + m2) * H_DIM + col] = v;
            }
        }
    }
}

// ---------------- kernel 6: combine (fp16 in, fp32 out) ----------------
__global__ void k_reduce(float* __restrict__ out) {
    int idx4 = blockIdx.x * blockDim.x + threadIdx.x;  // over T*H/4
    int t  = idx4 >> 9;
    int h4 = idx4 & 511;
    const int* ps = &g_pair2slot[t * TOPK];
    float4 s = make_float4(0.f, 0.f, 0.f, 0.f);
#pragma unroll
    for (int k = 0; k < TOPK; k++) {
        uint2 raw = *(const uint2*)&g_dbuf_h[(size_t)ps[k] * H_DIM + h4 * 4];
        __half2 p0 = *(__half2*)&raw.x;
        __half2 p1 = *(__half2*)&raw.y;
        float2 f0 = __half22float2(p0);
        float2 f1 = __half22float2(p1);
        s.x += f0.x; s.y += f0.y; s.z += f1.x; s.w += f1.y;
    }
    *(float4*)&out[(size_t)idx4 * 4] = s;
}

// ---------------- launch ----------------
extern "C" void kernel_launch(void* const* d_in, const int* in_sizes, int n_in,
                              void* d_out, int out_size) {
    const float* x  = (const float*)d_in[0];
    const float* gw = (const float*)d_in[1];
    const float* wg = (const float*)d_in[2];
    const float* wu = (const float*)d_in[3];
    const float* wd = (const float*)d_in[4];
    float* out = (float*)d_out;

    int write_ids = (out_size >= T_TOK * H_DIM + P_NUM) ? 1 : 0;

    const int smemA = (2 * AH_TILE + 4 * BGH_TILE) * 2;   // 73728 B -> 2 CTAs/SM
    const int smemB = (2 * AH_TILE + 2 * BBH_TILE) * 2;   // 73728 B -> 2 CTAs/SM
    cudaFuncSetAttribute(k_gemmA, cudaFuncAttributeMaxDynamicSharedMemorySize, smemA);
    cudaFuncSetAttribute(k_gemmB, cudaFuncAttributeMaxDynamicSharedMemorySize, smemB);

    int* cnt_p;
    cudaGetSymbolAddress((void**)&cnt_p, g_cnt);
    cudaMemsetAsync(cnt_p, 0, E_NUM * sizeof(int));

    __half* wg_h; __half* wu_h; __half* wd_h; __half* x_h;
    cudaGetSymbolAddress((void**)&wg_h, g_wg_h);
    cudaGetSymbolAddress((void**)&wu_h, g_wu_h);
    cudaGetSymbolAddress((void**)&wd_h, g_wd_h);
    cudaGetSymbolAddress((void**)&x_h,  g_x_h);

    k_router<<<T_TOK / 8, 256>>>(x, gw, out, write_ids);            // L1
    k_scan_scatter<<<1, 1024>>>();                                  // L2

    {
        dim3 g1(I_DIM / 32, H_DIM / 32, E_NUM);
        k_cvt_t2<<<g1, 256>>>(wg, wu, wg_h, wu_h, H_DIM, I_DIM);    // L3 (wg+wu fused)
    }

    dim3 ga(I_DIM / 64, T_TOK / 128, E_NUM);
    k_gemmA<<<ga, 256, smemA>>>(x_h, wg_h, wu_h);                   // L4 <- profile target

    {
        dim3 g2(H_DIM / 32, I_DIM / 32, E_NUM);
        k_cvt_t1<<<g2, 256>>>(wd, wd_h, I_DIM, H_DIM);              // L5
    }

    dim3 gb(H_DIM / 128, T_TOK / 128, E_NUM);
    k_gemmB<<<gb, 256, smemB>>>(wd_h);                              // L6

    k_reduce<<<(T_TOK * H_DIM / 4) / 256, 256>>>(out);              // L7
}